// round 2
// baseline (speedup 1.0000x reference)
#include <cuda_runtime.h>
#include <math.h>

#define HH 192
#define WWID 192
#define HW (192*192)
#define NB 4
#define ND 8

typedef unsigned long long ull;

// ---------------- f32x2 helpers ---------------------------------------------
__device__ __forceinline__ ull pack2(float lo, float hi) {
    ull r; asm("mov.b64 %0, {%1, %2};" : "=l"(r) : "f"(lo), "f"(hi)); return r;
}
__device__ __forceinline__ void unpack2(ull v, float& lo, float& hi) {
    asm("mov.b64 {%0, %1}, %2;" : "=f"(lo), "=f"(hi) : "l"(v));
}
__device__ __forceinline__ void fma2(ull& d, ull a, ull b) {
    asm("fma.rn.f32x2 %0, %1, %2, %0;" : "+l"(d) : "l"(a), "l"(b));
}

// ---------------- scratch (static device globals; no runtime alloc) ---------
__device__ float g_hs[NB * 8 * HW];      // h state
__device__ float g_r [NB * 40 * HW];     // [c_state(8) | q(32)]  (c carry = ch 0..7)
__device__ float g_gate[NB * 56 * HW];   // raw gate conv outputs (f,i,g,q)
__device__ float g_y0[NB * 40 * HW];     // conv0 raw output
__device__ float g_y1[NB * 40 * HW];     // conv1 raw output
__device__ float g_psum[2 * 40 * NB];    // [sum(40*NB) | sumsq(40*NB)]
__device__ float g_Wg[56 * 40 * 9];      // packed gate weights
__device__ float g_bg[56];               // packed gate biases

// ---------------- init ------------------------------------------------------
__global__ void zero_state() {
    int stride = gridDim.x * blockDim.x;
    int i0 = blockIdx.x * blockDim.x + threadIdx.x;
    for (int i = i0; i < NB * 8 * HW; i += stride) g_hs[i] = 0.f;
    for (int i = i0; i < NB * 40 * HW; i += stride) g_r[i] = 0.f;
}

__global__ void pack_gates(const float* __restrict__ Wf, const float* __restrict__ bf,
                           const float* __restrict__ Wi, const float* __restrict__ bi,
                           const float* __restrict__ Wc, const float* __restrict__ bc,
                           const float* __restrict__ Wq, const float* __restrict__ bq) {
    const int WSZ = 40 * 9;
    int i = blockIdx.x * blockDim.x + threadIdx.x;
    if (i < 56 * WSZ) {
        int cout = i / WSZ, rest = i - cout * WSZ;
        float v;
        if (cout < 8)       v = Wf[cout * WSZ + rest];
        else if (cout < 16) v = Wi[(cout - 8) * WSZ + rest];
        else if (cout < 24) v = Wc[(cout - 16) * WSZ + rest];
        else                v = Wq[(cout - 24) * WSZ + rest];
        g_Wg[i] = v;
    }
    if (i < 56) {
        float v;
        if (i < 8)       v = bf[i];
        else if (i < 16) v = bi[i - 8];
        else if (i < 24) v = bc[i - 16];
        else             v = bq[i - 24];
        g_bg[i] = v;
    }
}

// ---------------- generic direct conv (f32x2 packed) -------------------------
// Output tile: 32 x TILE_H per block. Threads (32, TY, CG).
// P = TILE_H/TY rows per thread (even); rows paired into P2 = P/2 f32x2 accums.
// Input channel c < CA from inA else inB (fused concat).
// PREOP: BN scale/shift computed in-block from psum/gamma/beta, then
//        v = relu(scale*v + shift) folded into the tile load.
template<int CIN, int CA, int COUT, int K, int TILE_H, int TY, int CG, bool PREOP, bool HASBIAS>
__global__ void __launch_bounds__(32 * TY * CG)
conv_generic(const float* __restrict__ inA, int strideA,
             const float* __restrict__ inB, int strideB,
             const float* __restrict__ wgt,   // [COUT, CIN, K, K]
             const float* __restrict__ bias,  // [COUT]
             const float* __restrict__ psum,  // [2*CIN*NB] raw sums (if PREOP)
             const float* __restrict__ gamma,
             const float* __restrict__ beta,
             float* __restrict__ out, int strideOut, int chanStrideOut)
{
    constexpr int P   = TILE_H / TY;
    constexpr int P2  = P / 2;
    constexpr int CPG = COUT / CG;
    constexpr int PAD = K / 2;
    constexpr int IN_TW = 32 + K - 1;
    constexpr int IN_TH = TILE_H + K - 1;
    constexpr int NT = 32 * TY * CG;

    __shared__ float  s_in[IN_TH * IN_TW];
    __shared__ float2 s_w2[COUT * K * K];
    __shared__ float  s_sc[CIN], s_sh[CIN];

    const int tx = threadIdx.x, ty = threadIdx.y, cg = threadIdx.z;
    const int tid = (cg * TY + ty) * 32 + tx;
    const int bx = blockIdx.x, by = blockIdx.y, n = blockIdx.z;
    const int gx = bx * 32 + tx;
    const int gy0 = by * TILE_H;

    if constexpr (PREOP) {
        if (tid < CIN) {
            float s = 0.f, s2 = 0.f;
#pragma unroll
            for (int nn = 0; nn < NB; nn++) {
                s  += psum[tid * NB + nn];
                s2 += psum[CIN * NB + tid * NB + nn];
            }
            const float Ninv = 1.f / (float)(NB * HW);
            float mean = s * Ninv;
            float var  = s2 * Ninv - mean * mean;
            float scv  = gamma[tid] * rsqrtf(var + 1e-5f);
            s_sc[tid] = scv;
            s_sh[tid] = beta[tid] - mean * scv;
        }
        __syncthreads();
    }

    ull acc[CPG][P2];
#pragma unroll
    for (int c = 0; c < CPG; c++)
#pragma unroll
        for (int p = 0; p < P2; p++) acc[c][p] = 0ull;

    for (int cin = 0; cin < CIN; cin++) {
        const float* src = (cin < CA)
            ? (inA + (size_t)n * strideA + (size_t)cin * HW)
            : (inB + (size_t)n * strideB + (size_t)(cin - CA) * HW);
        float sc = 1.f, sh = 0.f;
        if constexpr (PREOP) { sc = s_sc[cin]; sh = s_sh[cin]; }

        // stage input tile (+halo) for this input channel
        for (int idx = tid; idx < IN_TH * IN_TW; idx += NT) {
            int iy = idx / IN_TW, ix = idx - iy * IN_TW;
            int yy = gy0 + iy - PAD;
            int xx = bx * 32 + ix - PAD;
            float v = 0.f;
            if (yy >= 0 && yy < HH && xx >= 0 && xx < WWID) {
                v = src[yy * WWID + xx];
                if constexpr (PREOP) v = fmaxf(fmaf(sc, v, sh), 0.f);
            }
            s_in[idx] = v;
        }
        // stage this cin's weights for all couts, duplicated {w,w} for LDS.64
        for (int idx = tid; idx < COUT * K * K; idx += NT) {
            int cout = idx / (K * K);
            int k = idx - cout * (K * K);
            float w = wgt[((size_t)cout * CIN + cin) * (K * K) + k];
            s_w2[idx] = make_float2(w, w);
        }
        __syncthreads();

#pragma unroll
        for (int ky = 0; ky < K; ky++) {
            ull ivp[P2][K];
#pragma unroll
            for (int p = 0; p < P2; p++) {
                int r0 = ty + (2 * p) * TY + ky;
                int r1 = r0 + TY;
#pragma unroll
                for (int kx = 0; kx < K; kx++)
                    ivp[p][kx] = pack2(s_in[r0 * IN_TW + tx + kx],
                                       s_in[r1 * IN_TW + tx + kx]);
            }
#pragma unroll
            for (int c = 0; c < CPG; c++) {
                const ull* w2 = reinterpret_cast<const ull*>(
                    &s_w2[(cg * CPG + c) * (K * K) + ky * K]);
#pragma unroll
                for (int kx = 0; kx < K; kx++) {
                    ull wp = w2[kx];
#pragma unroll
                    for (int p = 0; p < P2; p++)
                        fma2(acc[c][p], ivp[p][kx], wp);
                }
            }
        }
        __syncthreads();
    }

#pragma unroll
    for (int c = 0; c < CPG; c++) {
        int cout = cg * CPG + c;
        float bv = 0.f;
        if constexpr (HASBIAS) bv = bias[cout];
        float* ob = out + (size_t)n * strideOut + (size_t)cout * chanStrideOut;
#pragma unroll
        for (int p = 0; p < P2; p++) {
            float lo, hi;
            unpack2(acc[c][p], lo, hi);
            int gyl = gy0 + ty + (2 * p) * TY;
            ob[gyl * WWID + gx] = lo + bv;
            ob[(gyl + TY) * WWID + gx] = hi + bv;
        }
    }
}

// ---------------- LSTM pointwise cell update --------------------------------
__device__ __forceinline__ float fsig(float x) {
    return __fdividef(1.f, 1.f + __expf(-x));
}
__device__ __forceinline__ float ftanh(float x) {
    return 1.f - __fdividef(2.f, __expf(2.f * x) + 1.f);
}

__global__ void cell_pointwise(const float* __restrict__ gate, float* __restrict__ r) {
    int i = blockIdx.x * blockDim.x + threadIdx.x;
    if (i >= NB * HW) return;
    int n = i / HW, p = i - n * HW;
    const float* gb = gate + (size_t)n * 56 * HW + p;
    float* rb = r + (size_t)n * 40 * HW + p;
#pragma unroll
    for (int c = 0; c < 8; c++) {
        float f  = fsig(gb[(size_t)c * HW]);
        float ii = fsig(gb[(size_t)(8 + c) * HW]);
        float gg = ftanh(gb[(size_t)(16 + c) * HW]);
        float cso = rb[(size_t)c * HW];
        rb[(size_t)c * HW] = f * cso + ii * gg;
    }
#pragma unroll
    for (int j = 0; j < 32; j++) {
        rb[(size_t)(8 + j) * HW] = fsig(gb[(size_t)(24 + j) * HW]);
    }
}

// ---------------- BN partial sums (per channel, per batch) ------------------
__global__ void bn_partial(const float* __restrict__ y, float* __restrict__ psum) {
    int c = blockIdx.x, n = blockIdx.y;
    const float4* yp = (const float4*)(y + ((size_t)n * 40 + c) * HW);
    float s = 0.f, s2 = 0.f;
    for (int i = threadIdx.x; i < HW / 4; i += blockDim.x) {
        float4 v = yp[i];
        s += v.x + v.y + v.z + v.w;
        s2 = fmaf(v.x, v.x, s2); s2 = fmaf(v.y, v.y, s2);
        s2 = fmaf(v.z, v.z, s2); s2 = fmaf(v.w, v.w, s2);
    }
    __shared__ float rs[256], rs2[256];
    rs[threadIdx.x] = s; rs2[threadIdx.x] = s2;
    __syncthreads();
    for (int off = 128; off > 0; off >>= 1) {
        if (threadIdx.x < off) {
            rs[threadIdx.x] += rs[threadIdx.x + off];
            rs2[threadIdx.x] += rs2[threadIdx.x + off];
        }
        __syncthreads();
    }
    if (threadIdx.x == 0) {
        psum[c * NB + n] = rs[0];
        psum[40 * NB + c * NB + n] = rs2[0];
    }
}

// ---------------- driver -----------------------------------------------------
extern "C" void kernel_launch(void* const* d_in, const int* in_sizes, int n_in,
                              void* d_out, int out_size) {
    const float* x1  = (const float*)d_in[0];
    const float* x2  = (const float*)d_in[1];
    const float* Wf  = (const float*)d_in[2];
    const float* bf  = (const float*)d_in[3];
    const float* Wi  = (const float*)d_in[4];
    const float* bi  = (const float*)d_in[5];
    const float* Wc  = (const float*)d_in[6];
    const float* bc  = (const float*)d_in[7];
    const float* Wq  = (const float*)d_in[8];
    const float* bq  = (const float*)d_in[9];
    const float* W0  = (const float*)d_in[10];
    const float* g0  = (const float*)d_in[11];
    const float* be0 = (const float*)d_in[12];
    const float* W1  = (const float*)d_in[13];
    const float* g1  = (const float*)d_in[14];
    const float* be1 = (const float*)d_in[15];
    const float* W2  = (const float*)d_in[16];
    const float* b2w = (const float*)d_in[17];
    const float* Wh  = (const float*)d_in[18];
    const float* bh  = (const float*)d_in[19];
    float* out = (float*)d_out;

    float *hs, *r, *gate, *y0, *y1, *psum, *Wg, *bg;
    cudaGetSymbolAddress((void**)&hs,   g_hs);
    cudaGetSymbolAddress((void**)&r,    g_r);
    cudaGetSymbolAddress((void**)&gate, g_gate);
    cudaGetSymbolAddress((void**)&y0,   g_y0);
    cudaGetSymbolAddress((void**)&y1,   g_y1);
    cudaGetSymbolAddress((void**)&psum, g_psum);
    cudaGetSymbolAddress((void**)&Wg,   g_Wg);
    cudaGetSymbolAddress((void**)&bg,   g_bg);

    zero_state<<<1024, 256>>>();
    pack_gates<<<(56 * 360 + 255) / 256, 256>>>(Wf, bf, Wi, bi, Wc, bc, Wq, bq);

    for (int t = 0; t < ND; t++) {
        for (int s = 0; s < 2; s++) {
            const float* x = (s == 0 ? x1 : x2) + (size_t)t * 32 * HW;

            // 1) gate conv 3x3: ic = [x(32) | hs(8)] -> 56 raw channels
            conv_generic<40, 32, 56, 3, 8, 2, 8, false, true>
                <<<dim3(6, 24, NB), dim3(32, 2, 8)>>>(
                    x, ND * 32 * HW, hs, 8 * HW, Wg, bg,
                    nullptr, nullptr, nullptr,
                    gate, 56 * HW, HW);

            // 2) LSTM pointwise: c' = sig(f)*c + sig(i)*tanh(g); r = [c' | sig(q)]
            cell_pointwise<<<(NB * HW + 255) / 256, 256>>>(gate, r);

            // 3) conv0 5x5 40->40 (raw; BN applied by consumer)
            conv_generic<40, 40, 40, 5, 16, 4, 4, false, false>
                <<<dim3(6, 12, NB), dim3(32, 4, 4)>>>(
                    r, 40 * HW, nullptr, 0, W0, nullptr,
                    nullptr, nullptr, nullptr,
                    y0, 40 * HW, HW);

            // 4) BN partial sums for y0
            bn_partial<<<dim3(40, NB), 256>>>(y0, psum);

            // 5) conv1 5x5 40->40, BN+ReLU of y0 fused into input load
            conv_generic<40, 40, 40, 5, 16, 4, 4, true, false>
                <<<dim3(6, 12, NB), dim3(32, 4, 4)>>>(
                    y0, 40 * HW, nullptr, 0, W1, nullptr,
                    psum, g0, be0,
                    y1, 40 * HW, HW);

            // 6) BN partial sums for y1
            bn_partial<<<dim3(40, NB), 256>>>(y1, psum);

            // 7) new h-state: conv 3x3 40->8 (BN+ReLU fused on input)
            conv_generic<40, 40, 8, 3, 16, 8, 2, true, true>
                <<<dim3(6, 12, NB), dim3(32, 8, 2)>>>(
                    y1, 40 * HW, nullptr, 0, Wh, bh,
                    psum, g1, be1,
                    hs, 8 * HW, HW);

            // 8) output head: conv 5x5 40->3 into d_out[(b,3,d,H,W)] slice
            conv_generic<40, 40, 3, 5, 16, 8, 1, true, true>
                <<<dim3(6, 12, NB), dim3(32, 8, 1)>>>(
                    y1, 40 * HW, nullptr, 0, W2, b2w,
                    psum, g1, be1,
                    out + (size_t)s * (NB * 3 * ND * HW) + (size_t)t * HW,
                    3 * ND * HW, ND * HW);
        }
    }
}

// round 5
// speedup vs baseline: 1.5979x; 1.5979x over previous
#include <cuda_runtime.h>
#include <cuda_bf16.h>
#include <cstdint>
#include <math.h>

#define HH 192
#define WWID 192
#define HW (192*192)
#define NB 4
#define ND 8

// ======================= mma / ldmatrix helpers (sm_80+ PTX) ================
__device__ __forceinline__ void ldmx4(uint32_t addr, uint32_t* r) {
    asm volatile("ldmatrix.sync.aligned.m8n8.x4.shared.b16 {%0,%1,%2,%3}, [%4];"
        : "=r"(r[0]), "=r"(r[1]), "=r"(r[2]), "=r"(r[3]) : "r"(addr));
}
__device__ __forceinline__ void mma16816(float* d, const uint32_t* a, uint2 b) {
    asm volatile("mma.sync.aligned.m16n8k16.row.col.f32.bf16.bf16.f32 "
        "{%0,%1,%2,%3}, {%4,%5,%6,%7}, {%8,%9}, {%0,%1,%2,%3};"
        : "+f"(d[0]), "+f"(d[1]), "+f"(d[2]), "+f"(d[3])
        : "r"(a[0]), "r"(a[1]), "r"(a[2]), "r"(a[3]), "r"(b.x), "r"(b.y));
}
__device__ __forceinline__ uint32_t smem_u32(const void* p) {
    uint32_t a;
    asm("{ .reg .u64 t; cvta.to.shared.u64 t, %1; cvt.u32.u64 %0, t; }" : "=r"(a) : "l"(p));
    return a;
}
__device__ __forceinline__ unsigned short bfbits(float v) {
    return __bfloat16_as_ushort(__float2bfloat16(v));
}

// ======================= scratch ============================================
__device__ float g_hs[NB * 8 * HW];
__device__ float g_r [NB * 40 * HW];
__device__ float g_gate[NB * 56 * HW];
__device__ float g_y0[NB * 40 * HW];
__device__ float g_y1[NB * 40 * HW];
__device__ float g_psum[2 * 40 * NB];
__device__ float g_Wg[56 * 40 * 9];
__device__ float g_bg[56];
// per-fragment packed bf16 weights: [tap(25)][kt(3)][nt(5)][term(2)][lane(32)] uint2
__device__ uint2 g_w0pk[25 * 3 * 5 * 2 * 32];
__device__ uint2 g_w1pk[25 * 3 * 5 * 2 * 32];

// ======================= init kernels =======================================
__global__ void zero_state() {
    int stride = gridDim.x * blockDim.x;
    int i0 = blockIdx.x * blockDim.x + threadIdx.x;
    for (int i = i0; i < NB * 8 * HW; i += stride) g_hs[i] = 0.f;
    for (int i = i0; i < NB * 40 * HW; i += stride) g_r[i] = 0.f;
}

__global__ void pack_gates(const float* __restrict__ Wf, const float* __restrict__ bf,
                           const float* __restrict__ Wi, const float* __restrict__ bi,
                           const float* __restrict__ Wc, const float* __restrict__ bc,
                           const float* __restrict__ Wq, const float* __restrict__ bq) {
    const int WSZ = 40 * 9;
    int i = blockIdx.x * blockDim.x + threadIdx.x;
    if (i < 56 * WSZ) {
        int cout = i / WSZ, rest = i - cout * WSZ;
        float v;
        if (cout < 8)       v = Wf[cout * WSZ + rest];
        else if (cout < 16) v = Wi[(cout - 8) * WSZ + rest];
        else if (cout < 24) v = Wc[(cout - 16) * WSZ + rest];
        else                v = Wq[(cout - 24) * WSZ + rest];
        g_Wg[i] = v;
    }
    if (i < 56) {
        float v;
        if (i < 8)       v = bf[i];
        else if (i < 16) v = bi[i - 8];
        else if (i < 24) v = bc[i - 16];
        else             v = bq[i - 24];
        g_bg[i] = v;
    }
}

// pack W[40][40][5][5] into per-mma-fragment b-frag layout, bf16 hi/lo split
__global__ void pack_w5_mma(const float* __restrict__ W, uint2* __restrict__ dst) {
    int i = blockIdx.x * blockDim.x + threadIdx.x;
    if (i >= 25 * 3 * 5 * 2 * 32) return;
    int lane = i & 31; int rest = i >> 5;
    int term = rest & 1; rest >>= 1;
    int nt = rest % 5;  rest /= 5;
    int kt = rest % 3;  int tap = rest / 3;
    int nn = nt * 8 + (lane >> 2);
    int k0 = kt * 16 + (lane & 3) * 2;
    unsigned short h[4];
#pragma unroll
    for (int j = 0; j < 4; j++) {
        int kk = k0 + (j & 1) + (j >> 1) * 8;
        float v = (kk < 40) ? W[(nn * 40 + kk) * 25 + tap] : 0.f;
        unsigned short hb = bfbits(v);
        if (term == 0) h[j] = hb;
        else {
            __nv_bfloat16 t = __ushort_as_bfloat16(hb);
            h[j] = bfbits(v - __bfloat162float(t));
        }
    }
    dst[i] = make_uint2((uint32_t)h[0] | ((uint32_t)h[1] << 16),
                        (uint32_t)h[2] | ((uint32_t)h[3] << 16));
}

// ======================= mma 5x5 conv (40->40, bf16 3-term split) ===========
// CTA: 128 thr (4 warps), out tile 32x4 pixels x 40 couts.
// A smem: 288 pixels (36x8 incl halo) x 48 cins, bf16 hi/lo planes, stride 56 h.
#define ASTRIDE 56
#define APLANE  (288 * ASTRIDE * 2)              // bytes per plane (32256)
#define MMA_SMEM (2 * APLANE)

template<bool PREOP>
__global__ void __launch_bounds__(128)
conv5x5_mma(const float* __restrict__ in,        // [NB][40][HW]
            const uint2* __restrict__ wpk,
            const float* __restrict__ psum,
            const float* __restrict__ gamma,
            const float* __restrict__ beta,
            float* __restrict__ out)             // [NB][40][HW]
{
    extern __shared__ char dsm[];
    __shared__ float s_sc[40], s_sh[40];
    __nv_bfloat16* Ah = (__nv_bfloat16*)dsm;
    __nv_bfloat16* Al = (__nv_bfloat16*)(dsm + APLANE);

    const int tid = threadIdx.x;
    const int w = tid >> 5, lane = tid & 31;
    const int bx = blockIdx.x, by = blockIdx.y, n = blockIdx.z;

    if constexpr (PREOP) {
        if (tid < 40) {
            float s = 0.f, s2 = 0.f;
#pragma unroll
            for (int nn = 0; nn < NB; nn++) {
                s  += psum[tid * NB + nn];
                s2 += psum[40 * NB + tid * NB + nn];
            }
            const float Ninv = 1.f / (float)(NB * HW);
            float mean = s * Ninv;
            float var  = s2 * Ninv - mean * mean;
            float scv  = gamma[tid] * rsqrtf(var + 1e-5f);
            s_sc[tid] = scv;
            s_sh[tid] = beta[tid] - mean * scv;
        }
        __syncthreads();
    }

    // zero K-pad (cins 40..47)
    for (int p = tid; p < 288; p += 128) {
#pragma unroll
        for (int k = 40; k < 48; k++) {
            Ah[p * ASTRIDE + k] = __ushort_as_bfloat16(0);
            Al[p * ASTRIDE + k] = __ushort_as_bfloat16(0);
        }
    }
    // stage input tile, split into bf16 hi/lo
    const int x0 = bx * 32 - 2, y0 = by * 4 - 2;
    for (int i = tid; i < 40 * 288; i += 128) {
        int cin = i / 288, pix = i - cin * 288;
        int pr = pix / 36, pc = pix - pr * 36;
        int yy = y0 + pr, xx = x0 + pc;
        float v = 0.f;
        if (yy >= 0 && yy < HH && xx >= 0 && xx < WWID) {
            v = in[((size_t)n * 40 + cin) * HW + yy * WWID + xx];
            if constexpr (PREOP) v = fmaxf(fmaf(s_sc[cin], v, s_sh[cin]), 0.f);
        }
        __nv_bfloat16 h = __float2bfloat16(v);
        __nv_bfloat16 l = __float2bfloat16(v - __bfloat162float(h));
        Ah[pix * ASTRIDE + cin] = h;
        Al[pix * ASTRIDE + cin] = l;
    }
    __syncthreads();

    const uint32_t ah_base = smem_u32(Ah);
    const uint32_t al_base = ah_base + APLANE;
    const int lrow = lane & 15;
    const int lcolB = (lane >> 4) * 16;          // byte offset for mat2/3 (k+8)

    float d[2][5][4];
#pragma unroll
    for (int mt = 0; mt < 2; mt++)
#pragma unroll
        for (int nt = 0; nt < 5; nt++)
#pragma unroll
            for (int j = 0; j < 4; j++) d[mt][nt][j] = 0.f;

    for (int tap = 0; tap < 25; tap++) {
        int ky = tap / 5, kx = tap - ky * 5;
        int rowbase = (w + ky) * 36 + kx;

        uint32_t a_h[3][2][4], a_l[3][2][4];
#pragma unroll
        for (int kt = 0; kt < 3; kt++)
#pragma unroll
            for (int mt = 0; mt < 2; mt++) {
                uint32_t off = (uint32_t)(rowbase + mt * 16 + lrow) * (ASTRIDE * 2)
                             + kt * 32 + lcolB;
                ldmx4(ah_base + off, a_h[kt][mt]);
                ldmx4(al_base + off, a_l[kt][mt]);
            }

        const uint2* wt = wpk + tap * (3 * 5 * 2 * 32);
#pragma unroll
        for (int kt = 0; kt < 3; kt++) {
#pragma unroll
            for (int nt = 0; nt < 5; nt++) {
                uint2 bh = wt[((kt * 5 + nt) * 2 + 0) * 32 + lane];
                uint2 bl = wt[((kt * 5 + nt) * 2 + 1) * 32 + lane];
#pragma unroll
                for (int mt = 0; mt < 2; mt++) {
                    mma16816(d[mt][nt], a_h[kt][mt], bh);
                    mma16816(d[mt][nt], a_l[kt][mt], bh);
                    mma16816(d[mt][nt], a_h[kt][mt], bl);
                }
            }
        }
    }

    // epilogue: D rows = pixel x, cols = cout
    const int gy = by * 4 + w;
#pragma unroll
    for (int mt = 0; mt < 2; mt++) {
        int gx = bx * 32 + mt * 16 + (lane >> 2);
#pragma unroll
        for (int nt = 0; nt < 5; nt++) {
            int c = nt * 8 + (lane & 3) * 2;
            float* ob = out + ((size_t)n * 40 + c) * HW + gy * WWID + gx;
            ob[0]       = d[mt][nt][0];
            ob[HW]      = d[mt][nt][1];
            ob[8]       = d[mt][nt][2];
            ob[HW + 8]  = d[mt][nt][3];
        }
    }
}

// ======================= scalar direct conv =================================
template<int CIN, int CA, int COUT, int K, int TILE_H, int TY, int CG, bool PREOP, bool HASBIAS>
__global__ void __launch_bounds__(32 * TY * CG)
conv_generic(const float* __restrict__ inA, int strideA,
             const float* __restrict__ inB, int strideB,
             const float* __restrict__ wgt,
             const float* __restrict__ bias,
             const float* __restrict__ psum,
             const float* __restrict__ gamma,
             const float* __restrict__ beta,
             float* __restrict__ out, int strideOut, int chanStrideOut)
{
    constexpr int P = TILE_H / TY;
    constexpr int CPG = COUT / CG;
    constexpr int PAD = K / 2;
    constexpr int IN_TW = 32 + K - 1;
    constexpr int IN_TH = TILE_H + K - 1;
    constexpr int NT = 32 * TY * CG;

    __shared__ float s_in[IN_TH * IN_TW];
    __shared__ float s_w[COUT * K * K];
    __shared__ float s_sc[CIN], s_sh[CIN];

    const int tx = threadIdx.x, ty = threadIdx.y, cg = threadIdx.z;
    const int tid = (cg * TY + ty) * 32 + tx;
    const int bx = blockIdx.x, by = blockIdx.y, n = blockIdx.z;
    const int gx = bx * 32 + tx;
    const int gy0 = by * TILE_H;

    if constexpr (PREOP) {
        if (tid < CIN) {
            float s = 0.f, s2 = 0.f;
#pragma unroll
            for (int nn = 0; nn < NB; nn++) {
                s  += psum[tid * NB + nn];
                s2 += psum[CIN * NB + tid * NB + nn];
            }
            const float Ninv = 1.f / (float)(NB * HW);
            float mean = s * Ninv;
            float var  = s2 * Ninv - mean * mean;
            float scv  = gamma[tid] * rsqrtf(var + 1e-5f);
            s_sc[tid] = scv;
            s_sh[tid] = beta[tid] - mean * scv;
        }
        __syncthreads();
    }

    float acc[CPG][P];
#pragma unroll
    for (int c = 0; c < CPG; c++)
#pragma unroll
        for (int p = 0; p < P; p++) acc[c][p] = 0.f;

    for (int cin = 0; cin < CIN; cin++) {
        const float* src = (cin < CA)
            ? (inA + (size_t)n * strideA + (size_t)cin * HW)
            : (inB + (size_t)n * strideB + (size_t)(cin - CA) * HW);
        float sc = 1.f, sh = 0.f;
        if constexpr (PREOP) { sc = s_sc[cin]; sh = s_sh[cin]; }

        for (int idx = tid; idx < IN_TH * IN_TW; idx += NT) {
            int iy = idx / IN_TW, ix = idx - iy * IN_TW;
            int yy = gy0 + iy - PAD;
            int xx = bx * 32 + ix - PAD;
            float v = 0.f;
            if (yy >= 0 && yy < HH && xx >= 0 && xx < WWID) {
                v = src[yy * WWID + xx];
                if constexpr (PREOP) v = fmaxf(fmaf(sc, v, sh), 0.f);
            }
            s_in[idx] = v;
        }
        for (int idx = tid; idx < COUT * K * K; idx += NT) {
            int cout = idx / (K * K);
            int k = idx - cout * (K * K);
            s_w[idx] = wgt[((size_t)cout * CIN + cin) * (K * K) + k];
        }
        __syncthreads();

#pragma unroll
        for (int ky = 0; ky < K; ky++) {
            float iv[P][K];
#pragma unroll
            for (int p = 0; p < P; p++) {
                int row = ty + p * TY + ky;
#pragma unroll
                for (int kx = 0; kx < K; kx++)
                    iv[p][kx] = s_in[row * IN_TW + tx + kx];
            }
#pragma unroll
            for (int c = 0; c < CPG; c++) {
                const float* wrow = &s_w[(cg * CPG + c) * (K * K) + ky * K];
#pragma unroll
                for (int kx = 0; kx < K; kx++) {
                    float wv = wrow[kx];
#pragma unroll
                    for (int p = 0; p < P; p++)
                        acc[c][p] = fmaf(iv[p][kx], wv, acc[c][p]);
                }
            }
        }
        __syncthreads();
    }

#pragma unroll
    for (int c = 0; c < CPG; c++) {
        int cout = cg * CPG + c;
        float bv = 0.f;
        if constexpr (HASBIAS) bv = bias[cout];
#pragma unroll
        for (int p = 0; p < P; p++) {
            int gy = gy0 + ty + p * TY;
            out[(size_t)n * strideOut + (size_t)cout * chanStrideOut + gy * WWID + gx]
                = acc[c][p] + bv;
        }
    }
}

// ======================= LSTM pointwise =====================================
__device__ __forceinline__ float fsig(float x) {
    return __fdividef(1.f, 1.f + __expf(-x));
}
__device__ __forceinline__ float ftanh(float x) {
    return 1.f - __fdividef(2.f, __expf(2.f * x) + 1.f);
}

__global__ void cell_pointwise(const float* __restrict__ gate, float* __restrict__ r) {
    int i = blockIdx.x * blockDim.x + threadIdx.x;
    if (i >= NB * HW) return;
    int n = i / HW, p = i - n * HW;
    const float* gb = gate + (size_t)n * 56 * HW + p;
    float* rb = r + (size_t)n * 40 * HW + p;
#pragma unroll
    for (int c = 0; c < 8; c++) {
        float f  = fsig(gb[(size_t)c * HW]);
        float ii = fsig(gb[(size_t)(8 + c) * HW]);
        float gg = ftanh(gb[(size_t)(16 + c) * HW]);
        float cso = rb[(size_t)c * HW];
        rb[(size_t)c * HW] = f * cso + ii * gg;
    }
#pragma unroll
    for (int j = 0; j < 32; j++) {
        rb[(size_t)(8 + j) * HW] = fsig(gb[(size_t)(24 + j) * HW]);
    }
}

// ======================= BN partial sums ====================================
__global__ void bn_partial(const float* __restrict__ y, float* __restrict__ psum) {
    int c = blockIdx.x, n = blockIdx.y;
    const float4* yp = (const float4*)(y + ((size_t)n * 40 + c) * HW);
    float s = 0.f, s2 = 0.f;
    for (int i = threadIdx.x; i < HW / 4; i += blockDim.x) {
        float4 v = yp[i];
        s += v.x + v.y + v.z + v.w;
        s2 = fmaf(v.x, v.x, s2); s2 = fmaf(v.y, v.y, s2);
        s2 = fmaf(v.z, v.z, s2); s2 = fmaf(v.w, v.w, s2);
    }
    __shared__ float rs[256], rs2[256];
    rs[threadIdx.x] = s; rs2[threadIdx.x] = s2;
    __syncthreads();
    for (int off = 128; off > 0; off >>= 1) {
        if (threadIdx.x < off) {
            rs[threadIdx.x] += rs[threadIdx.x + off];
            rs2[threadIdx.x] += rs2[threadIdx.x + off];
        }
        __syncthreads();
    }
    if (threadIdx.x == 0) {
        psum[c * NB + n] = rs[0];
        psum[40 * NB + c * NB + n] = rs2[0];
    }
}

// ======================= driver =============================================
extern "C" void kernel_launch(void* const* d_in, const int* in_sizes, int n_in,
                              void* d_out, int out_size) {
    const float* x1  = (const float*)d_in[0];
    const float* x2  = (const float*)d_in[1];
    const float* Wf  = (const float*)d_in[2];
    const float* bf  = (const float*)d_in[3];
    const float* Wi  = (const float*)d_in[4];
    const float* bi  = (const float*)d_in[5];
    const float* Wc  = (const float*)d_in[6];
    const float* bc  = (const float*)d_in[7];
    const float* Wq  = (const float*)d_in[8];
    const float* bq  = (const float*)d_in[9];
    const float* W0  = (const float*)d_in[10];
    const float* g0  = (const float*)d_in[11];
    const float* be0 = (const float*)d_in[12];
    const float* W1  = (const float*)d_in[13];
    const float* g1  = (const float*)d_in[14];
    const float* be1 = (const float*)d_in[15];
    const float* W2  = (const float*)d_in[16];
    const float* b2w = (const float*)d_in[17];
    const float* Wh  = (const float*)d_in[18];
    const float* bh  = (const float*)d_in[19];
    float* out = (float*)d_out;

    float *hs, *r, *gate, *y0, *y1, *psum, *Wg, *bg;
    uint2 *w0pk, *w1pk;
    cudaGetSymbolAddress((void**)&hs,   g_hs);
    cudaGetSymbolAddress((void**)&r,    g_r);
    cudaGetSymbolAddress((void**)&gate, g_gate);
    cudaGetSymbolAddress((void**)&y0,   g_y0);
    cudaGetSymbolAddress((void**)&y1,   g_y1);
    cudaGetSymbolAddress((void**)&psum, g_psum);
    cudaGetSymbolAddress((void**)&Wg,   g_Wg);
    cudaGetSymbolAddress((void**)&bg,   g_bg);
    cudaGetSymbolAddress((void**)&w0pk, g_w0pk);
    cudaGetSymbolAddress((void**)&w1pk, g_w1pk);

    cudaFuncSetAttribute(conv5x5_mma<false>, cudaFuncAttributeMaxDynamicSharedMemorySize, MMA_SMEM);
    cudaFuncSetAttribute(conv5x5_mma<true>,  cudaFuncAttributeMaxDynamicSharedMemorySize, MMA_SMEM);

    zero_state<<<1024, 256>>>();
    pack_gates<<<(56 * 360 + 255) / 256, 256>>>(Wf, bf, Wi, bi, Wc, bc, Wq, bq);
    pack_w5_mma<<<(25 * 3 * 5 * 2 * 32 + 255) / 256, 256>>>(W0, w0pk);
    pack_w5_mma<<<(25 * 3 * 5 * 2 * 32 + 255) / 256, 256>>>(W1, w1pk);

    for (int t = 0; t < ND; t++) {
        for (int s = 0; s < 2; s++) {
            const float* x = (s == 0 ? x1 : x2) + (size_t)t * 32 * HW;

            // 1) gate conv 3x3: [x(32)|hs(8)] -> 56 raw channels
            conv_generic<40, 32, 56, 3, 8, 2, 8, false, true>
                <<<dim3(6, 24, NB), dim3(32, 2, 8)>>>(
                    x, ND * 32 * HW, hs, 8 * HW, Wg, bg,
                    nullptr, nullptr, nullptr, gate, 56 * HW, HW);

            // 2) LSTM pointwise
            cell_pointwise<<<(NB * HW + 255) / 256, 256>>>(gate, r);

            // 3) conv0 5x5 40->40 (mma, raw output)
            conv5x5_mma<false><<<dim3(6, 48, NB), 128, MMA_SMEM>>>(
                r, w0pk, nullptr, nullptr, nullptr, y0);

            // 4) BN partials for y0
            bn_partial<<<dim3(40, NB), 256>>>(y0, psum);

            // 5) conv1 5x5 40->40 (mma, BN+ReLU of y0 fused on input)
            conv5x5_mma<true><<<dim3(6, 48, NB), 128, MMA_SMEM>>>(
                y0, w1pk, psum, g0, be0, y1);

            // 6) BN partials for y1
            bn_partial<<<dim3(40, NB), 256>>>(y1, psum);

            // 7) new h-state: conv 3x3 40->8 (BN+ReLU fused on input)
            conv_generic<40, 40, 8, 3, 16, 8, 2, true, true>
                <<<dim3(6, 12, NB), dim3(32, 8, 2)>>>(
                    y1, 40 * HW, nullptr, 0, Wh, bh,
                    psum, g1, be1, hs, 8 * HW, HW);

            // 8) output head: conv 5x5 40->3 into d_out (b,3,d,H,W) slice
            conv_generic<40, 40, 3, 5, 16, 8, 1, true, true>
                <<<dim3(6, 12, NB), dim3(32, 8, 1)>>>(
                    y1, 40 * HW, nullptr, 0, W2, b2w,
                    psum, g1, be1,
                    out + (size_t)s * (NB * 3 * ND * HW) + (size_t)t * HW,
                    3 * ND * HW, ND * HW);
        }
    }
}

// round 6
// speedup vs baseline: 1.9928x; 1.2471x over previous
#include <cuda_runtime.h>
#include <cuda_bf16.h>
#include <cstdint>
#include <math.h>

#define HH 192
#define WWID 192
#define HW (192*192)
#define NB 4
#define ND 8

// ======================= mma / ldmatrix helpers (sm_80+ PTX) ================
__device__ __forceinline__ void ldmx4(uint32_t addr, uint32_t* r) {
    asm volatile("ldmatrix.sync.aligned.m8n8.x4.shared.b16 {%0,%1,%2,%3}, [%4];"
        : "=r"(r[0]), "=r"(r[1]), "=r"(r[2]), "=r"(r[3]) : "r"(addr));
}
__device__ __forceinline__ void ldmx2(uint32_t addr, uint32_t* r) {
    asm volatile("ldmatrix.sync.aligned.m8n8.x2.shared.b16 {%0,%1}, [%2];"
        : "=r"(r[0]), "=r"(r[1]) : "r"(addr));
}
__device__ __forceinline__ void mma16816(float* d, const uint32_t* a, uint2 b) {
    asm volatile("mma.sync.aligned.m16n8k16.row.col.f32.bf16.bf16.f32 "
        "{%0,%1,%2,%3}, {%4,%5,%6,%7}, {%8,%9}, {%0,%1,%2,%3};"
        : "+f"(d[0]), "+f"(d[1]), "+f"(d[2]), "+f"(d[3])
        : "r"(a[0]), "r"(a[1]), "r"(a[2]), "r"(a[3]), "r"(b.x), "r"(b.y));
}
__device__ __forceinline__ void mma1688(float* d, const uint32_t* a, uint32_t b) {
    asm volatile("mma.sync.aligned.m16n8k8.row.col.f32.bf16.bf16.f32 "
        "{%0,%1,%2,%3}, {%4,%5}, {%6}, {%0,%1,%2,%3};"
        : "+f"(d[0]), "+f"(d[1]), "+f"(d[2]), "+f"(d[3])
        : "r"(a[0]), "r"(a[1]), "r"(b));
}
__device__ __forceinline__ uint32_t smem_u32(const void* p) {
    uint32_t a;
    asm("{ .reg .u64 t; cvta.to.shared.u64 t, %1; cvt.u32.u64 %0, t; }" : "=r"(a) : "l"(p));
    return a;
}
__device__ __forceinline__ unsigned short bfbits(float v) {
    return __bfloat16_as_ushort(__float2bfloat16(v));
}
__device__ __forceinline__ float fsig(float x) {
    return __fdividef(1.f, 1.f + __expf(-x));
}
__device__ __forceinline__ float ftanh(float x) {
    return 1.f - __fdividef(2.f, __expf(2.f * x) + 1.f);
}

// ======================= scratch ============================================
__device__ float g_hs[NB * 8 * HW];
__device__ float g_r [NB * 40 * HW];     // [c_state(8) | q(32)]
__device__ float g_y0[NB * 40 * HW];
__device__ float g_y1[NB * 40 * HW];
__device__ float g_psum[2 * 40 * NB];
__device__ float g_Wg[56 * 40 * 9];
__device__ float g_bg[56];
// packed mma weight fragments (k16 pairs + k8 tail), bf16 hi/lo terms
__device__ uint2    g_w0k16[25 * 2 * 5 * 2 * 32];
__device__ uint32_t g_w0k8 [25 * 5 * 2 * 32];
__device__ uint2    g_w1k16[25 * 2 * 5 * 2 * 32];
__device__ uint32_t g_w1k8 [25 * 5 * 2 * 32];
__device__ uint2    g_wgk16[9 * 2 * 7 * 2 * 32];
__device__ uint32_t g_wgk8 [9 * 7 * 2 * 32];

// ======================= init kernels =======================================
__global__ void zero_state() {
    int stride = gridDim.x * blockDim.x;
    int i0 = blockIdx.x * blockDim.x + threadIdx.x;
    for (int i = i0; i < NB * 8 * HW; i += stride) g_hs[i] = 0.f;
    for (int i = i0; i < NB * 40 * HW; i += stride) g_r[i] = 0.f;
}

__global__ void pack_gates(const float* __restrict__ Wf, const float* __restrict__ bf,
                           const float* __restrict__ Wi, const float* __restrict__ bi,
                           const float* __restrict__ Wc, const float* __restrict__ bc,
                           const float* __restrict__ Wq, const float* __restrict__ bq) {
    const int WSZ = 40 * 9;
    int i = blockIdx.x * blockDim.x + threadIdx.x;
    if (i < 56 * WSZ) {
        int cout = i / WSZ, rest = i - cout * WSZ;
        float v;
        if (cout < 8)       v = Wf[cout * WSZ + rest];
        else if (cout < 16) v = Wi[(cout - 8) * WSZ + rest];
        else if (cout < 24) v = Wc[(cout - 16) * WSZ + rest];
        else                v = Wq[(cout - 24) * WSZ + rest];
        g_Wg[i] = v;
    }
    if (i < 56) {
        float v;
        if (i < 8)       v = bf[i];
        else if (i < 16) v = bi[i - 8];
        else if (i < 24) v = bc[i - 16];
        else             v = bq[i - 24];
        g_bg[i] = v;
    }
}

// W layout expected: W[(n*40 + k)*TAPS + tap]
template<int TAPS, int NT>
__global__ void pack_k16(const float* __restrict__ W, uint2* __restrict__ dst) {
    int i = blockIdx.x * blockDim.x + threadIdx.x;
    if (i >= TAPS * 2 * NT * 2 * 32) return;
    int lane = i & 31; int r = i >> 5;
    int term = r & 1; r >>= 1;
    int nt = r % NT;  r /= NT;
    int kt = r & 1;   int tap = r >> 1;
    int nn = nt * 8 + (lane >> 2);
    int k0 = kt * 16 + (lane & 3) * 2;
    unsigned short h[4];
#pragma unroll
    for (int j = 0; j < 4; j++) {
        int kk = k0 + (j & 1) + (j >> 1) * 8;
        float v = W[(nn * 40 + kk) * TAPS + tap];
        unsigned short hb = bfbits(v);
        if (term == 0) h[j] = hb;
        else h[j] = bfbits(v - __bfloat162float(__ushort_as_bfloat16(hb)));
    }
    dst[i] = make_uint2((uint32_t)h[0] | ((uint32_t)h[1] << 16),
                        (uint32_t)h[2] | ((uint32_t)h[3] << 16));
}

template<int TAPS, int NT>
__global__ void pack_k8(const float* __restrict__ W, uint32_t* __restrict__ dst) {
    int i = blockIdx.x * blockDim.x + threadIdx.x;
    if (i >= TAPS * NT * 2 * 32) return;
    int lane = i & 31; int r = i >> 5;
    int term = r & 1; r >>= 1;
    int nt = r % NT;  int tap = r / NT;
    int nn = nt * 8 + (lane >> 2);
    int k0 = 32 + (lane & 3) * 2;
    unsigned short h[2];
#pragma unroll
    for (int j = 0; j < 2; j++) {
        int kk = k0 + j;
        float v = W[(nn * 40 + kk) * TAPS + tap];
        unsigned short hb = bfbits(v);
        if (term == 0) h[j] = hb;
        else h[j] = bfbits(v - __bfloat162float(__ushort_as_bfloat16(hb)));
    }
    dst[i] = (uint32_t)h[0] | ((uint32_t)h[1] << 16);
}

// ======================= generic mma conv (CIN=40, bf16 3-term, K=40) =======
// CTA: 128 thr / 4 warps; out tile 32x4 pixels; COUT = NT*8.
// LSTM: epilogue runs the LSTM cell pointwise; out = r buffer (old c in ch0-7).
#define ASTRIDE 56

template<int KK, int NT, int CA, bool PREOP, bool LSTM>
__global__ void __launch_bounds__(128)
conv_mma(const float* __restrict__ inA, int strideA,
         const float* __restrict__ inB, int strideB,
         const uint2* __restrict__ wk16,
         const uint32_t* __restrict__ wk8,
         const float* __restrict__ bias,     // LSTM gate biases
         const float* __restrict__ psum,
         const float* __restrict__ gamma,
         const float* __restrict__ beta,
         float* __restrict__ out)
{
    constexpr int TW = 32 + KK - 1;
    constexpr int TH = 4 + KK - 1;
    constexpr int NPIX = TW * TH;
    constexpr int PADK = KK / 2;
    constexpr int APL = NPIX * ASTRIDE * 2;     // bytes per bf16 plane

    extern __shared__ char dsm[];
    __shared__ float s_sc[40], s_sh[40];
    __shared__ float s_bias[56];
    __nv_bfloat16* Ah = (__nv_bfloat16*)dsm;
    __nv_bfloat16* Al = (__nv_bfloat16*)(dsm + APL);

    const int tid = threadIdx.x;
    const int w = tid >> 5, lane = tid & 31;
    const int bx = blockIdx.x, by = blockIdx.y, n = blockIdx.z;

    if constexpr (LSTM) {
        if (tid < 56) s_bias[tid] = bias[tid];
    }
    if constexpr (PREOP) {
        if (tid < 40) {
            float s = 0.f, s2 = 0.f;
#pragma unroll
            for (int nn = 0; nn < NB; nn++) {
                s  += psum[tid * NB + nn];
                s2 += psum[40 * NB + tid * NB + nn];
            }
            const float Ninv = 1.f / (float)(NB * HW);
            float mean = s * Ninv;
            float var  = s2 * Ninv - mean * mean;
            float scv  = gamma[tid] * rsqrtf(var + 1e-5f);
            s_sc[tid] = scv;
            s_sh[tid] = beta[tid] - mean * scv;
        }
        __syncthreads();
    }

    // ---- stage input tile (fused concat), split bf16 hi/lo -----------------
    const int x0 = bx * 32 - PADK, y0 = by * 4 - PADK;
    for (int i = tid; i < 40 * NPIX; i += 128) {
        int cin = i / NPIX, pix = i - cin * NPIX;
        int pr = pix / TW, pc = pix - pr * TW;
        int yy = y0 + pr, xx = x0 + pc;
        float v = 0.f;
        if (yy >= 0 && yy < HH && xx >= 0 && xx < WWID) {
            const float* src = (cin < CA)
                ? (inA + (size_t)n * strideA + (size_t)cin * HW)
                : (inB + (size_t)n * strideB + (size_t)(cin - CA) * HW);
            v = src[yy * WWID + xx];
            if constexpr (PREOP) v = fmaxf(fmaf(s_sc[cin], v, s_sh[cin]), 0.f);
        }
        __nv_bfloat16 h = __float2bfloat16(v);
        __nv_bfloat16 l = __float2bfloat16(v - __bfloat162float(h));
        Ah[pix * ASTRIDE + cin] = h;
        Al[pix * ASTRIDE + cin] = l;
    }
    __syncthreads();

    const uint32_t ah_base = smem_u32(Ah);
    const uint32_t al_base = ah_base + APL;
    const int lrow = lane & 15;
    const int lcolB = (lane >> 4) * 16;

    float d[2][NT][4];
#pragma unroll
    for (int mt = 0; mt < 2; mt++)
#pragma unroll
        for (int nt = 0; nt < NT; nt++)
#pragma unroll
            for (int j = 0; j < 4; j++) d[mt][nt][j] = 0.f;

    for (int tap = 0; tap < KK * KK; tap++) {
        int ky = tap / KK, kx = tap - ky * KK;
        int rowbase = (w + ky) * TW + kx;

        uint32_t a_h[2][2][4], a_l[2][2][4];   // [kt][mt]
        uint32_t a_h8[2][2], a_l8[2][2];       // [mt]
#pragma unroll
        for (int mt = 0; mt < 2; mt++) {
            uint32_t rb = (uint32_t)(rowbase + mt * 16 + lrow) * (ASTRIDE * 2);
            ldmx4(ah_base + rb + lcolB, a_h[0][mt]);
            ldmx4(ah_base + rb + 32 + lcolB, a_h[1][mt]);
            ldmx2(ah_base + rb + 64, a_h8[mt]);
            ldmx4(al_base + rb + lcolB, a_l[0][mt]);
            ldmx4(al_base + rb + 32 + lcolB, a_l[1][mt]);
            ldmx2(al_base + rb + 64, a_l8[mt]);
        }

        const uint2* wt16 = wk16 + tap * (2 * NT * 2 * 32);
        const uint32_t* wt8 = wk8 + tap * (NT * 2 * 32);
#pragma unroll
        for (int kt = 0; kt < 2; kt++) {
#pragma unroll
            for (int nt = 0; nt < NT; nt++) {
                uint2 bh = wt16[((kt * NT + nt) * 2 + 0) * 32 + lane];
                uint2 bl = wt16[((kt * NT + nt) * 2 + 1) * 32 + lane];
#pragma unroll
                for (int mt = 0; mt < 2; mt++) {
                    mma16816(d[mt][nt], a_h[kt][mt], bh);
                    mma16816(d[mt][nt], a_l[kt][mt], bh);
                    mma16816(d[mt][nt], a_h[kt][mt], bl);
                }
            }
        }
#pragma unroll
        for (int nt = 0; nt < NT; nt++) {
            uint32_t bh8 = wt8[(nt * 2 + 0) * 32 + lane];
            uint32_t bl8 = wt8[(nt * 2 + 1) * 32 + lane];
#pragma unroll
            for (int mt = 0; mt < 2; mt++) {
                mma1688(d[mt][nt], a_h8[mt], bh8);
                mma1688(d[mt][nt], a_l8[mt], bh8);
                mma1688(d[mt][nt], a_h8[mt], bl8);
            }
        }
    }

    if constexpr (LSTM) {
        // ---- stash D (128 pix x 56 ch) to smem, then LSTM pointwise --------
        __syncthreads();                      // A planes dead; reuse dsm
        float* sd = (float*)dsm;              // [128][57]
#pragma unroll
        for (int mt = 0; mt < 2; mt++) {
            int px = mt * 16 + (lane >> 2);
#pragma unroll
            for (int nt = 0; nt < NT; nt++) {
                int c = nt * 8 + (lane & 3) * 2;
                sd[(w * 32 + px) * 57 + c]           = d[mt][nt][0];
                sd[(w * 32 + px) * 57 + c + 1]       = d[mt][nt][1];
                sd[(w * 32 + px + 8) * 57 + c]       = d[mt][nt][2];
                sd[(w * 32 + px + 8) * 57 + c + 1]   = d[mt][nt][3];
            }
        }
        __syncthreads();
        const float* sp = sd + tid * 57;
        int gy = by * 4 + (tid >> 5);
        int gx = bx * 32 + (tid & 31);
        float* rb = out + (size_t)n * 40 * HW + gy * WWID + gx;
#pragma unroll
        for (int c = 0; c < 8; c++) {
            float f  = fsig(sp[c] + s_bias[c]);
            float ii = fsig(sp[8 + c] + s_bias[8 + c]);
            float gg = ftanh(sp[16 + c] + s_bias[16 + c]);
            float co = rb[(size_t)c * HW];
            rb[(size_t)c * HW] = f * co + ii * gg;
        }
#pragma unroll
        for (int j = 0; j < 32; j++) {
            rb[(size_t)(8 + j) * HW] = fsig(sp[24 + j] + s_bias[24 + j]);
        }
    } else {
        const int gy = by * 4 + w;
#pragma unroll
        for (int mt = 0; mt < 2; mt++) {
            int gx = bx * 32 + mt * 16 + (lane >> 2);
#pragma unroll
            for (int nt = 0; nt < NT; nt++) {
                int c = nt * 8 + (lane & 3) * 2;
                float* ob = out + ((size_t)n * 40 + c) * HW + gy * WWID + gx;
                ob[0]      = d[mt][nt][0];
                ob[HW]     = d[mt][nt][1];
                ob[8]      = d[mt][nt][2];
                ob[HW + 8] = d[mt][nt][3];
            }
        }
    }
}

#define GATE_SMEM (34 * 6 * ASTRIDE * 2 * 2 > 128 * 57 * 4 ? 34 * 6 * ASTRIDE * 2 * 2 : 128 * 57 * 4)
#define C5_SMEM   (36 * 8 * ASTRIDE * 2 * 2)

// ======================= scalar direct conv (small tails) ===================
template<int CIN, int CA, int COUT, int K, int TILE_H, int TY, int CG, bool PREOP, bool HASBIAS>
__global__ void __launch_bounds__(32 * TY * CG)
conv_generic(const float* __restrict__ inA, int strideA,
             const float* __restrict__ inB, int strideB,
             const float* __restrict__ wgt,
             const float* __restrict__ bias,
             const float* __restrict__ psum,
             const float* __restrict__ gamma,
             const float* __restrict__ beta,
             float* __restrict__ out, int strideOut, int chanStrideOut)
{
    constexpr int P = TILE_H / TY;
    constexpr int CPG = COUT / CG;
    constexpr int PAD = K / 2;
    constexpr int IN_TW = 32 + K - 1;
    constexpr int IN_TH = TILE_H + K - 1;
    constexpr int NT = 32 * TY * CG;

    __shared__ float s_in[IN_TH * IN_TW];
    __shared__ float s_w[COUT * K * K];
    __shared__ float s_sc[CIN], s_sh[CIN];

    const int tx = threadIdx.x, ty = threadIdx.y, cg = threadIdx.z;
    const int tid = (cg * TY + ty) * 32 + tx;
    const int bx = blockIdx.x, by = blockIdx.y, n = blockIdx.z;
    const int gx = bx * 32 + tx;
    const int gy0 = by * TILE_H;

    if constexpr (PREOP) {
        if (tid < CIN) {
            float s = 0.f, s2 = 0.f;
#pragma unroll
            for (int nn = 0; nn < NB; nn++) {
                s  += psum[tid * NB + nn];
                s2 += psum[CIN * NB + tid * NB + nn];
            }
            const float Ninv = 1.f / (float)(NB * HW);
            float mean = s * Ninv;
            float var  = s2 * Ninv - mean * mean;
            float scv  = gamma[tid] * rsqrtf(var + 1e-5f);
            s_sc[tid] = scv;
            s_sh[tid] = beta[tid] - mean * scv;
        }
        __syncthreads();
    }

    float acc[CPG][P];
#pragma unroll
    for (int c = 0; c < CPG; c++)
#pragma unroll
        for (int p = 0; p < P; p++) acc[c][p] = 0.f;

    for (int cin = 0; cin < CIN; cin++) {
        const float* src = (cin < CA)
            ? (inA + (size_t)n * strideA + (size_t)cin * HW)
            : (inB + (size_t)n * strideB + (size_t)(cin - CA) * HW);
        float sc = 1.f, sh = 0.f;
        if constexpr (PREOP) { sc = s_sc[cin]; sh = s_sh[cin]; }

        for (int idx = tid; idx < IN_TH * IN_TW; idx += NT) {
            int iy = idx / IN_TW, ix = idx - iy * IN_TW;
            int yy = gy0 + iy - PAD;
            int xx = bx * 32 + ix - PAD;
            float v = 0.f;
            if (yy >= 0 && yy < HH && xx >= 0 && xx < WWID) {
                v = src[yy * WWID + xx];
                if constexpr (PREOP) v = fmaxf(fmaf(sc, v, sh), 0.f);
            }
            s_in[idx] = v;
        }
        for (int idx = tid; idx < COUT * K * K; idx += NT) {
            int cout = idx / (K * K);
            int k = idx - cout * (K * K);
            s_w[idx] = wgt[((size_t)cout * CIN + cin) * (K * K) + k];
        }
        __syncthreads();

#pragma unroll
        for (int ky = 0; ky < K; ky++) {
            float iv[P][K];
#pragma unroll
            for (int p = 0; p < P; p++) {
                int row = ty + p * TY + ky;
#pragma unroll
                for (int kx = 0; kx < K; kx++)
                    iv[p][kx] = s_in[row * IN_TW + tx + kx];
            }
#pragma unroll
            for (int c = 0; c < CPG; c++) {
                const float* wrow = &s_w[(cg * CPG + c) * (K * K) + ky * K];
#pragma unroll
                for (int kx = 0; kx < K; kx++) {
                    float wv = wrow[kx];
#pragma unroll
                    for (int p = 0; p < P; p++)
                        acc[c][p] = fmaf(iv[p][kx], wv, acc[c][p]);
                }
            }
        }
        __syncthreads();
    }

#pragma unroll
    for (int c = 0; c < CPG; c++) {
        int cout = cg * CPG + c;
        float bv = 0.f;
        if constexpr (HASBIAS) bv = bias[cout];
#pragma unroll
        for (int p = 0; p < P; p++) {
            int gy = gy0 + ty + p * TY;
            out[(size_t)n * strideOut + (size_t)cout * chanStrideOut + gy * WWID + gx]
                = acc[c][p] + bv;
        }
    }
}

// ======================= BN partial sums ====================================
__global__ void bn_partial(const float* __restrict__ y, float* __restrict__ psum) {
    int c = blockIdx.x, n = blockIdx.y;
    const float4* yp = (const float4*)(y + ((size_t)n * 40 + c) * HW);
    float s = 0.f, s2 = 0.f;
    for (int i = threadIdx.x; i < HW / 4; i += blockDim.x) {
        float4 v = yp[i];
        s += v.x + v.y + v.z + v.w;
        s2 = fmaf(v.x, v.x, s2); s2 = fmaf(v.y, v.y, s2);
        s2 = fmaf(v.z, v.z, s2); s2 = fmaf(v.w, v.w, s2);
    }
    __shared__ float rs[256], rs2[256];
    rs[threadIdx.x] = s; rs2[threadIdx.x] = s2;
    __syncthreads();
    for (int off = 128; off > 0; off >>= 1) {
        if (threadIdx.x < off) {
            rs[threadIdx.x] += rs[threadIdx.x + off];
            rs2[threadIdx.x] += rs2[threadIdx.x + off];
        }
        __syncthreads();
    }
    if (threadIdx.x == 0) {
        psum[c * NB + n] = rs[0];
        psum[40 * NB + c * NB + n] = rs2[0];
    }
}

// ======================= driver =============================================
extern "C" void kernel_launch(void* const* d_in, const int* in_sizes, int n_in,
                              void* d_out, int out_size) {
    const float* x1  = (const float*)d_in[0];
    const float* x2  = (const float*)d_in[1];
    const float* Wf  = (const float*)d_in[2];
    const float* bf  = (const float*)d_in[3];
    const float* Wi  = (const float*)d_in[4];
    const float* bi  = (const float*)d_in[5];
    const float* Wc  = (const float*)d_in[6];
    const float* bc  = (const float*)d_in[7];
    const float* Wq  = (const float*)d_in[8];
    const float* bq  = (const float*)d_in[9];
    const float* W0  = (const float*)d_in[10];
    const float* g0  = (const float*)d_in[11];
    const float* be0 = (const float*)d_in[12];
    const float* W1  = (const float*)d_in[13];
    const float* g1  = (const float*)d_in[14];
    const float* be1 = (const float*)d_in[15];
    const float* W2  = (const float*)d_in[16];
    const float* b2w = (const float*)d_in[17];
    const float* Wh  = (const float*)d_in[18];
    const float* bh  = (const float*)d_in[19];
    float* out = (float*)d_out;

    float *hs, *r, *y0, *y1, *psum, *Wg, *bg;
    uint2 *w0k16, *w1k16, *wgk16;
    uint32_t *w0k8, *w1k8, *wgk8;
    cudaGetSymbolAddress((void**)&hs,    g_hs);
    cudaGetSymbolAddress((void**)&r,     g_r);
    cudaGetSymbolAddress((void**)&y0,    g_y0);
    cudaGetSymbolAddress((void**)&y1,    g_y1);
    cudaGetSymbolAddress((void**)&psum,  g_psum);
    cudaGetSymbolAddress((void**)&Wg,    g_Wg);
    cudaGetSymbolAddress((void**)&bg,    g_bg);
    cudaGetSymbolAddress((void**)&w0k16, g_w0k16);
    cudaGetSymbolAddress((void**)&w0k8,  g_w0k8);
    cudaGetSymbolAddress((void**)&w1k16, g_w1k16);
    cudaGetSymbolAddress((void**)&w1k8,  g_w1k8);
    cudaGetSymbolAddress((void**)&wgk16, g_wgk16);
    cudaGetSymbolAddress((void**)&wgk8,  g_wgk8);

    cudaFuncSetAttribute((const void*)conv_mma<3, 7, 32, false, true>,
                         cudaFuncAttributeMaxDynamicSharedMemorySize, GATE_SMEM);
    cudaFuncSetAttribute((const void*)conv_mma<5, 5, 40, false, false>,
                         cudaFuncAttributeMaxDynamicSharedMemorySize, C5_SMEM);
    cudaFuncSetAttribute((const void*)conv_mma<5, 5, 40, true, false>,
                         cudaFuncAttributeMaxDynamicSharedMemorySize, C5_SMEM);

    zero_state<<<1024, 256>>>();
    pack_gates<<<(56 * 360 + 255) / 256, 256>>>(Wf, bf, Wi, bi, Wc, bc, Wq, bq);
    pack_k16<25, 5><<<(25 * 2 * 5 * 2 * 32 + 255) / 256, 256>>>(W0, w0k16);
    pack_k8 <25, 5><<<(25 * 5 * 2 * 32 + 255) / 256, 256>>>(W0, w0k8);
    pack_k16<25, 5><<<(25 * 2 * 5 * 2 * 32 + 255) / 256, 256>>>(W1, w1k16);
    pack_k8 <25, 5><<<(25 * 5 * 2 * 32 + 255) / 256, 256>>>(W1, w1k8);
    pack_k16<9, 7><<<(9 * 2 * 7 * 2 * 32 + 255) / 256, 256>>>(Wg, wgk16);
    pack_k8 <9, 7><<<(9 * 7 * 2 * 32 + 255) / 256, 256>>>(Wg, wgk8);

    for (int t = 0; t < ND; t++) {
        for (int s = 0; s < 2; s++) {
            const float* x = (s == 0 ? x1 : x2) + (size_t)t * 32 * HW;

            // 1) gate conv 3x3 (mma) + fused LSTM pointwise -> r = [c'|sig(q)]
            conv_mma<3, 7, 32, false, true>
                <<<dim3(6, 48, NB), 128, GATE_SMEM>>>(
                    x, ND * 32 * HW, hs, 8 * HW, wgk16, wgk8, bg,
                    nullptr, nullptr, nullptr, r);

            // 2) conv0 5x5 40->40 (mma, raw output)
            conv_mma<5, 5, 40, false, false>
                <<<dim3(6, 48, NB), 128, C5_SMEM>>>(
                    r, 40 * HW, nullptr, 0, w0k16, w0k8, nullptr,
                    nullptr, nullptr, nullptr, y0);

            // 3) BN partials for y0
            bn_partial<<<dim3(40, NB), 256>>>(y0, psum);

            // 4) conv1 5x5 40->40 (mma, BN+ReLU of y0 fused on input)
            conv_mma<5, 5, 40, true, false>
                <<<dim3(6, 48, NB), 128, C5_SMEM>>>(
                    y0, 40 * HW, nullptr, 0, w1k16, w1k8, nullptr,
                    psum, g0, be0, y1);

            // 5) BN partials for y1
            bn_partial<<<dim3(40, NB), 256>>>(y1, psum);

            // 6) new h-state: conv 3x3 40->8 (BN+ReLU fused on input)
            conv_generic<40, 40, 8, 3, 16, 8, 2, true, true>
                <<<dim3(6, 12, NB), dim3(32, 8, 2)>>>(
                    y1, 40 * HW, nullptr, 0, Wh, bh,
                    psum, g1, be1, hs, 8 * HW, HW);

            // 7) output head: conv 5x5 40->3 into d_out (b,3,d,H,W) slice
            conv_generic<40, 40, 3, 5, 16, 8, 1, true, true>
                <<<dim3(6, 12, NB), dim3(32, 8, 1)>>>(
                    y1, 40 * HW, nullptr, 0, W2, b2w,
                    psum, g1, be1,
                    out + (size_t)s * (NB * 3 * ND * HW) + (size_t)t * HW,
                    3 * ND * HW, ND * HW);
        }
    }
}

// round 7
// speedup vs baseline: 2.0052x; 1.0062x over previous
#include <cuda_runtime.h>
#include <cuda_bf16.h>
#include <cstdint>
#include <math.h>

#define HH 192
#define WWID 192
#define HW (192*192)
#define NB 4
#define ND 8

// ======================= mma / ldmatrix helpers (sm_80+ PTX) ================
__device__ __forceinline__ void ldmx4(uint32_t addr, uint32_t* r) {
    asm volatile("ldmatrix.sync.aligned.m8n8.x4.shared.b16 {%0,%1,%2,%3}, [%4];"
        : "=r"(r[0]), "=r"(r[1]), "=r"(r[2]), "=r"(r[3]) : "r"(addr));
}
__device__ __forceinline__ void ldmx2(uint32_t addr, uint32_t* r) {
    asm volatile("ldmatrix.sync.aligned.m8n8.x2.shared.b16 {%0,%1}, [%2];"
        : "=r"(r[0]), "=r"(r[1]) : "r"(addr));
}
__device__ __forceinline__ void mma16816(float* d, const uint32_t* a, uint2 b) {
    asm volatile("mma.sync.aligned.m16n8k16.row.col.f32.bf16.bf16.f32 "
        "{%0,%1,%2,%3}, {%4,%5,%6,%7}, {%8,%9}, {%0,%1,%2,%3};"
        : "+f"(d[0]), "+f"(d[1]), "+f"(d[2]), "+f"(d[3])
        : "r"(a[0]), "r"(a[1]), "r"(a[2]), "r"(a[3]), "r"(b.x), "r"(b.y));
}
__device__ __forceinline__ void mma1688(float* d, const uint32_t* a, uint32_t b) {
    asm volatile("mma.sync.aligned.m16n8k8.row.col.f32.bf16.bf16.f32 "
        "{%0,%1,%2,%3}, {%4,%5}, {%6}, {%0,%1,%2,%3};"
        : "+f"(d[0]), "+f"(d[1]), "+f"(d[2]), "+f"(d[3])
        : "r"(a[0]), "r"(a[1]), "r"(b));
}
__device__ __forceinline__ uint32_t smem_u32(const void* p) {
    uint32_t a;
    asm("{ .reg .u64 t; cvta.to.shared.u64 t, %1; cvt.u32.u64 %0, t; }" : "=r"(a) : "l"(p));
    return a;
}
__device__ __forceinline__ unsigned short bfbits(float v) {
    return __bfloat16_as_ushort(__float2bfloat16(v));
}
__device__ __forceinline__ float fsig(float x) {
    return __fdividef(1.f, 1.f + __expf(-x));
}
__device__ __forceinline__ float ftanh(float x) {
    return 1.f - __fdividef(2.f, __expf(2.f * x) + 1.f);
}

// ======================= scratch ============================================
__device__ float g_hs[NB * 8 * HW];
__device__ float g_r [NB * 40 * HW];     // [c_state(8) | q(32)]
__device__ float g_y0[NB * 40 * HW];
__device__ float g_y1[NB * 40 * HW];
__device__ float g_psum[2 * 40 * NB];
__device__ float g_Wg[56 * 40 * 9];
__device__ float g_bg[56];
// packed mma weight fragments (k16 pairs + k8 tail), bf16 hi/lo terms
__device__ uint2    g_w0k16[25 * 2 * 5 * 2 * 32];
__device__ uint32_t g_w0k8 [25 * 5 * 2 * 32];
__device__ uint2    g_w1k16[25 * 2 * 5 * 2 * 32];
__device__ uint32_t g_w1k8 [25 * 5 * 2 * 32];
__device__ uint2    g_wgk16[9 * 2 * 7 * 2 * 32];
__device__ uint32_t g_wgk8 [9 * 7 * 2 * 32];

// ======================= init kernels =======================================
__global__ void zero_state() {
    int stride = gridDim.x * blockDim.x;
    int i0 = blockIdx.x * blockDim.x + threadIdx.x;
    for (int i = i0; i < NB * 8 * HW; i += stride) g_hs[i] = 0.f;
    for (int i = i0; i < NB * 40 * HW; i += stride) g_r[i] = 0.f;
}

__global__ void pack_gates(const float* __restrict__ Wf, const float* __restrict__ bf,
                           const float* __restrict__ Wi, const float* __restrict__ bi,
                           const float* __restrict__ Wc, const float* __restrict__ bc,
                           const float* __restrict__ Wq, const float* __restrict__ bq) {
    const int WSZ = 40 * 9;
    int i = blockIdx.x * blockDim.x + threadIdx.x;
    if (i < 56 * WSZ) {
        int cout = i / WSZ, rest = i - cout * WSZ;
        float v;
        if (cout < 8)       v = Wf[cout * WSZ + rest];
        else if (cout < 16) v = Wi[(cout - 8) * WSZ + rest];
        else if (cout < 24) v = Wc[(cout - 16) * WSZ + rest];
        else                v = Wq[(cout - 24) * WSZ + rest];
        g_Wg[i] = v;
    }
    if (i < 56) {
        float v;
        if (i < 8)       v = bf[i];
        else if (i < 16) v = bi[i - 8];
        else if (i < 24) v = bc[i - 16];
        else             v = bq[i - 24];
        g_bg[i] = v;
    }
}

// W layout expected: W[(n*40 + k)*TAPS + tap]
template<int TAPS, int NT>
__global__ void pack_k16(const float* __restrict__ W, uint2* __restrict__ dst) {
    int i = blockIdx.x * blockDim.x + threadIdx.x;
    if (i >= TAPS * 2 * NT * 2 * 32) return;
    int lane = i & 31; int r = i >> 5;
    int term = r & 1; r >>= 1;
    int nt = r % NT;  r /= NT;
    int kt = r & 1;   int tap = r >> 1;
    int nn = nt * 8 + (lane >> 2);
    int k0 = kt * 16 + (lane & 3) * 2;
    unsigned short h[4];
#pragma unroll
    for (int j = 0; j < 4; j++) {
        int kk = k0 + (j & 1) + (j >> 1) * 8;
        float v = W[(nn * 40 + kk) * TAPS + tap];
        unsigned short hb = bfbits(v);
        if (term == 0) h[j] = hb;
        else h[j] = bfbits(v - __bfloat162float(__ushort_as_bfloat16(hb)));
    }
    dst[i] = make_uint2((uint32_t)h[0] | ((uint32_t)h[1] << 16),
                        (uint32_t)h[2] | ((uint32_t)h[3] << 16));
}

template<int TAPS, int NT>
__global__ void pack_k8(const float* __restrict__ W, uint32_t* __restrict__ dst) {
    int i = blockIdx.x * blockDim.x + threadIdx.x;
    if (i >= TAPS * NT * 2 * 32) return;
    int lane = i & 31; int r = i >> 5;
    int term = r & 1; r >>= 1;
    int nt = r % NT;  int tap = r / NT;
    int nn = nt * 8 + (lane >> 2);
    int k0 = 32 + (lane & 3) * 2;
    unsigned short h[2];
#pragma unroll
    for (int j = 0; j < 2; j++) {
        int kk = k0 + j;
        float v = W[(nn * 40 + kk) * TAPS + tap];
        unsigned short hb = bfbits(v);
        if (term == 0) h[j] = hb;
        else h[j] = bfbits(v - __bfloat162float(__ushort_as_bfloat16(hb)));
    }
    dst[i] = (uint32_t)h[0] | ((uint32_t)h[1] << 16);
}

// ======================= generic mma conv (CIN=40, bf16 3-term, K=40) =======
// CTA: 128 thr / 4 warps; out tile 32x4 pixels; COUT = NT*8.
// LSTM: epilogue runs the LSTM cell pointwise; out = r buffer (old c in ch0-7).
#define ASTRIDE 56

template<int KK, int NT, int CA, bool PREOP, bool LSTM>
__global__ void __launch_bounds__(128)
conv_mma(const float* __restrict__ inA, int strideA,
         const float* __restrict__ inB, int strideB,
         const uint2* __restrict__ wk16,
         const uint32_t* __restrict__ wk8,
         const float* __restrict__ bias,     // LSTM gate biases
         const float* __restrict__ psum,
         const float* __restrict__ gamma,
         const float* __restrict__ beta,
         float* __restrict__ out)
{
    constexpr int TW = 32 + KK - 1;
    constexpr int TH = 4 + KK - 1;
    constexpr int NPIX = TW * TH;
    constexpr int PADK = KK / 2;
    constexpr int APL = NPIX * ASTRIDE * 2;     // bytes per bf16 plane

    extern __shared__ char dsm[];
    __shared__ float s_sc[40], s_sh[40];
    __shared__ float s_bias[56];
    __nv_bfloat16* Ah = (__nv_bfloat16*)dsm;
    __nv_bfloat16* Al = (__nv_bfloat16*)(dsm + APL);

    const int tid = threadIdx.x;
    const int w = tid >> 5, lane = tid & 31;
    const int bx = blockIdx.x, by = blockIdx.y, n = blockIdx.z;

    if constexpr (LSTM) {
        if (tid < 56) s_bias[tid] = bias[tid];
    }
    if constexpr (PREOP) {
        if (tid < 40) {
            float s = 0.f, s2 = 0.f;
#pragma unroll
            for (int nn = 0; nn < NB; nn++) {
                s  += psum[tid * NB + nn];
                s2 += psum[40 * NB + tid * NB + nn];
            }
            const float Ninv = 1.f / (float)(NB * HW);
            float mean = s * Ninv;
            float var  = s2 * Ninv - mean * mean;
            float scv  = gamma[tid] * rsqrtf(var + 1e-5f);
            s_sc[tid] = scv;
            s_sh[tid] = beta[tid] - mean * scv;
        }
        __syncthreads();
    }

    // ---- stage input tile (fused concat), split bf16 hi/lo -----------------
    const int x0 = bx * 32 - PADK, y0 = by * 4 - PADK;
    for (int i = tid; i < 40 * NPIX; i += 128) {
        int cin = i / NPIX, pix = i - cin * NPIX;
        int pr = pix / TW, pc = pix - pr * TW;
        int yy = y0 + pr, xx = x0 + pc;
        float v = 0.f;
        if (yy >= 0 && yy < HH && xx >= 0 && xx < WWID) {
            const float* src = (cin < CA)
                ? (inA + (size_t)n * strideA + (size_t)cin * HW)
                : (inB + (size_t)n * strideB + (size_t)(cin - CA) * HW);
            v = src[yy * WWID + xx];
            if constexpr (PREOP) v = fmaxf(fmaf(s_sc[cin], v, s_sh[cin]), 0.f);
        }
        __nv_bfloat16 h = __float2bfloat16(v);
        __nv_bfloat16 l = __float2bfloat16(v - __bfloat162float(h));
        Ah[pix * ASTRIDE + cin] = h;
        Al[pix * ASTRIDE + cin] = l;
    }
    __syncthreads();

    const uint32_t ah_base = smem_u32(Ah);
    const uint32_t al_base = ah_base + APL;
    const int lrow = lane & 15;
    const int lcolB = (lane >> 4) * 16;

    float d[2][NT][4];
#pragma unroll
    for (int mt = 0; mt < 2; mt++)
#pragma unroll
        for (int nt = 0; nt < NT; nt++)
#pragma unroll
            for (int j = 0; j < 4; j++) d[mt][nt][j] = 0.f;

    for (int tap = 0; tap < KK * KK; tap++) {
        int ky = tap / KK, kx = tap - ky * KK;
        int rowbase = (w + ky) * TW + kx;

        uint32_t a_h[2][2][4], a_l[2][2][4];   // [kt][mt]
        uint32_t a_h8[2][2], a_l8[2][2];       // [mt]
#pragma unroll
        for (int mt = 0; mt < 2; mt++) {
            uint32_t rb = (uint32_t)(rowbase + mt * 16 + lrow) * (ASTRIDE * 2);
            ldmx4(ah_base + rb + lcolB, a_h[0][mt]);
            ldmx4(ah_base + rb + 32 + lcolB, a_h[1][mt]);
            ldmx2(ah_base + rb + 64, a_h8[mt]);
            ldmx4(al_base + rb + lcolB, a_l[0][mt]);
            ldmx4(al_base + rb + 32 + lcolB, a_l[1][mt]);
            ldmx2(al_base + rb + 64, a_l8[mt]);
        }

        const uint2* wt16 = wk16 + tap * (2 * NT * 2 * 32);
        const uint32_t* wt8 = wk8 + tap * (NT * 2 * 32);
#pragma unroll
        for (int kt = 0; kt < 2; kt++) {
#pragma unroll
            for (int nt = 0; nt < NT; nt++) {
                uint2 bh = wt16[((kt * NT + nt) * 2 + 0) * 32 + lane];
                uint2 bl = wt16[((kt * NT + nt) * 2 + 1) * 32 + lane];
#pragma unroll
                for (int mt = 0; mt < 2; mt++) {
                    mma16816(d[mt][nt], a_h[kt][mt], bh);
                    mma16816(d[mt][nt], a_l[kt][mt], bh);
                    mma16816(d[mt][nt], a_h[kt][mt], bl);
                }
            }
        }
#pragma unroll
        for (int nt = 0; nt < NT; nt++) {
            uint32_t bh8 = wt8[(nt * 2 + 0) * 32 + lane];
            uint32_t bl8 = wt8[(nt * 2 + 1) * 32 + lane];
#pragma unroll
            for (int mt = 0; mt < 2; mt++) {
                mma1688(d[mt][nt], a_h8[mt], bh8);
                mma1688(d[mt][nt], a_l8[mt], bh8);
                mma1688(d[mt][nt], a_h8[mt], bl8);
            }
        }
    }

    if constexpr (LSTM) {
        // ---- stash D (128 pix x 56 ch) to smem, then LSTM pointwise --------
        __syncthreads();                      // A planes dead; reuse dsm
        float* sd = (float*)dsm;              // [128][57]
#pragma unroll
        for (int mt = 0; mt < 2; mt++) {
            int px = mt * 16 + (lane >> 2);
#pragma unroll
            for (int nt = 0; nt < NT; nt++) {
                int c = nt * 8 + (lane & 3) * 2;
                sd[(w * 32 + px) * 57 + c]           = d[mt][nt][0];
                sd[(w * 32 + px) * 57 + c + 1]       = d[mt][nt][1];
                sd[(w * 32 + px + 8) * 57 + c]       = d[mt][nt][2];
                sd[(w * 32 + px + 8) * 57 + c + 1]   = d[mt][nt][3];
            }
        }
        __syncthreads();
        const float* sp = sd + tid * 57;
        int gy = by * 4 + (tid >> 5);
        int gx = bx * 32 + (tid & 31);
        float* rb = out + (size_t)n * 40 * HW + gy * WWID + gx;
#pragma unroll
        for (int c = 0; c < 8; c++) {
            float f  = fsig(sp[c] + s_bias[c]);
            float ii = fsig(sp[8 + c] + s_bias[8 + c]);
            float gg = ftanh(sp[16 + c] + s_bias[16 + c]);
            float co = rb[(size_t)c * HW];
            rb[(size_t)c * HW] = f * co + ii * gg;
        }
#pragma unroll
        for (int j = 0; j < 32; j++) {
            rb[(size_t)(8 + j) * HW] = fsig(sp[24 + j] + s_bias[24 + j]);
        }
    } else {
        const int gy = by * 4 + w;
#pragma unroll
        for (int mt = 0; mt < 2; mt++) {
            int gx = bx * 32 + mt * 16 + (lane >> 2);
#pragma unroll
            for (int nt = 0; nt < NT; nt++) {
                int c = nt * 8 + (lane & 3) * 2;
                float* ob = out + ((size_t)n * 40 + c) * HW + gy * WWID + gx;
                ob[0]      = d[mt][nt][0];
                ob[HW]     = d[mt][nt][1];
                ob[8]      = d[mt][nt][2];
                ob[HW + 8] = d[mt][nt][3];
            }
        }
    }
}

#define GATE_SMEM (34 * 6 * ASTRIDE * 2 * 2 > 128 * 57 * 4 ? 34 * 6 * ASTRIDE * 2 * 2 : 128 * 57 * 4)
#define C5_SMEM   (36 * 8 * ASTRIDE * 2 * 2)

// ======================= scalar direct conv (small tails) ===================
template<int CIN, int CA, int COUT, int K, int TILE_H, int TY, int CG, bool PREOP, bool HASBIAS>
__global__ void __launch_bounds__(32 * TY * CG)
conv_generic(const float* __restrict__ inA, int strideA,
             const float* __restrict__ inB, int strideB,
             const float* __restrict__ wgt,
             const float* __restrict__ bias,
             const float* __restrict__ psum,
             const float* __restrict__ gamma,
             const float* __restrict__ beta,
             float* __restrict__ out, int strideOut, int chanStrideOut)
{
    constexpr int P = TILE_H / TY;
    constexpr int CPG = COUT / CG;
    constexpr int PAD = K / 2;
    constexpr int IN_TW = 32 + K - 1;
    constexpr int IN_TH = TILE_H + K - 1;
    constexpr int NT = 32 * TY * CG;

    __shared__ float s_in[IN_TH * IN_TW];
    __shared__ float s_w[COUT * K * K];
    __shared__ float s_sc[CIN], s_sh[CIN];

    const int tx = threadIdx.x, ty = threadIdx.y, cg = threadIdx.z;
    const int tid = (cg * TY + ty) * 32 + tx;
    const int bx = blockIdx.x, by = blockIdx.y, n = blockIdx.z;
    const int gx = bx * 32 + tx;
    const int gy0 = by * TILE_H;

    if constexpr (PREOP) {
        if (tid < CIN) {
            float s = 0.f, s2 = 0.f;
#pragma unroll
            for (int nn = 0; nn < NB; nn++) {
                s  += psum[tid * NB + nn];
                s2 += psum[CIN * NB + tid * NB + nn];
            }
            const float Ninv = 1.f / (float)(NB * HW);
            float mean = s * Ninv;
            float var  = s2 * Ninv - mean * mean;
            float scv  = gamma[tid] * rsqrtf(var + 1e-5f);
            s_sc[tid] = scv;
            s_sh[tid] = beta[tid] - mean * scv;
        }
        __syncthreads();
    }

    float acc[CPG][P];
#pragma unroll
    for (int c = 0; c < CPG; c++)
#pragma unroll
        for (int p = 0; p < P; p++) acc[c][p] = 0.f;

    for (int cin = 0; cin < CIN; cin++) {
        const float* src = (cin < CA)
            ? (inA + (size_t)n * strideA + (size_t)cin * HW)
            : (inB + (size_t)n * strideB + (size_t)(cin - CA) * HW);
        float sc = 1.f, sh = 0.f;
        if constexpr (PREOP) { sc = s_sc[cin]; sh = s_sh[cin]; }

        for (int idx = tid; idx < IN_TH * IN_TW; idx += NT) {
            int iy = idx / IN_TW, ix = idx - iy * IN_TW;
            int yy = gy0 + iy - PAD;
            int xx = bx * 32 + ix - PAD;
            float v = 0.f;
            if (yy >= 0 && yy < HH && xx >= 0 && xx < WWID) {
                v = src[yy * WWID + xx];
                if constexpr (PREOP) v = fmaxf(fmaf(sc, v, sh), 0.f);
            }
            s_in[idx] = v;
        }
        for (int idx = tid; idx < COUT * K * K; idx += NT) {
            int cout = idx / (K * K);
            int k = idx - cout * (K * K);
            s_w[idx] = wgt[((size_t)cout * CIN + cin) * (K * K) + k];
        }
        __syncthreads();

#pragma unroll
        for (int ky = 0; ky < K; ky++) {
            float iv[P][K];
#pragma unroll
            for (int p = 0; p < P; p++) {
                int row = ty + p * TY + ky;
#pragma unroll
                for (int kx = 0; kx < K; kx++)
                    iv[p][kx] = s_in[row * IN_TW + tx + kx];
            }
#pragma unroll
            for (int c = 0; c < CPG; c++) {
                const float* wrow = &s_w[(cg * CPG + c) * (K * K) + ky * K];
#pragma unroll
                for (int kx = 0; kx < K; kx++) {
                    float wv = wrow[kx];
#pragma unroll
                    for (int p = 0; p < P; p++)
                        acc[c][p] = fmaf(iv[p][kx], wv, acc[c][p]);
                }
            }
        }
        __syncthreads();
    }

#pragma unroll
    for (int c = 0; c < CPG; c++) {
        int cout = cg * CPG + c;
        float bv = 0.f;
        if constexpr (HASBIAS) bv = bias[cout];
#pragma unroll
        for (int p = 0; p < P; p++) {
            int gy = gy0 + ty + p * TY;
            out[(size_t)n * strideOut + (size_t)cout * chanStrideOut + gy * WWID + gx]
                = acc[c][p] + bv;
        }
    }
}

// ======================= BN partial sums ====================================
__global__ void bn_partial(const float* __restrict__ y, float* __restrict__ psum) {
    int c = blockIdx.x, n = blockIdx.y;
    const float4* yp = (const float4*)(y + ((size_t)n * 40 + c) * HW);
    float s = 0.f, s2 = 0.f;
    for (int i = threadIdx.x; i < HW / 4; i += blockDim.x) {
        float4 v = yp[i];
        s += v.x + v.y + v.z + v.w;
        s2 = fmaf(v.x, v.x, s2); s2 = fmaf(v.y, v.y, s2);
        s2 = fmaf(v.z, v.z, s2); s2 = fmaf(v.w, v.w, s2);
    }
    __shared__ float rs[256], rs2[256];
    rs[threadIdx.x] = s; rs2[threadIdx.x] = s2;
    __syncthreads();
    for (int off = 128; off > 0; off >>= 1) {
        if (threadIdx.x < off) {
            rs[threadIdx.x] += rs[threadIdx.x + off];
            rs2[threadIdx.x] += rs2[threadIdx.x + off];
        }
        __syncthreads();
    }
    if (threadIdx.x == 0) {
        psum[c * NB + n] = rs[0];
        psum[40 * NB + c * NB + n] = rs2[0];
    }
}

// ======================= driver =============================================
extern "C" void kernel_launch(void* const* d_in, const int* in_sizes, int n_in,
                              void* d_out, int out_size) {
    const float* x1  = (const float*)d_in[0];
    const float* x2  = (const float*)d_in[1];
    const float* Wf  = (const float*)d_in[2];
    const float* bf  = (const float*)d_in[3];
    const float* Wi  = (const float*)d_in[4];
    const float* bi  = (const float*)d_in[5];
    const float* Wc  = (const float*)d_in[6];
    const float* bc  = (const float*)d_in[7];
    const float* Wq  = (const float*)d_in[8];
    const float* bq  = (const float*)d_in[9];
    const float* W0  = (const float*)d_in[10];
    const float* g0  = (const float*)d_in[11];
    const float* be0 = (const float*)d_in[12];
    const float* W1  = (const float*)d_in[13];
    const float* g1  = (const float*)d_in[14];
    const float* be1 = (const float*)d_in[15];
    const float* W2  = (const float*)d_in[16];
    const float* b2w = (const float*)d_in[17];
    const float* Wh  = (const float*)d_in[18];
    const float* bh  = (const float*)d_in[19];
    float* out = (float*)d_out;

    float *hs, *r, *y0, *y1, *psum, *Wg, *bg;
    uint2 *w0k16, *w1k16, *wgk16;
    uint32_t *w0k8, *w1k8, *wgk8;
    cudaGetSymbolAddress((void**)&hs,    g_hs);
    cudaGetSymbolAddress((void**)&r,     g_r);
    cudaGetSymbolAddress((void**)&y0,    g_y0);
    cudaGetSymbolAddress((void**)&y1,    g_y1);
    cudaGetSymbolAddress((void**)&psum,  g_psum);
    cudaGetSymbolAddress((void**)&Wg,    g_Wg);
    cudaGetSymbolAddress((void**)&bg,    g_bg);
    cudaGetSymbolAddress((void**)&w0k16, g_w0k16);
    cudaGetSymbolAddress((void**)&w0k8,  g_w0k8);
    cudaGetSymbolAddress((void**)&w1k16, g_w1k16);
    cudaGetSymbolAddress((void**)&w1k8,  g_w1k8);
    cudaGetSymbolAddress((void**)&wgk16, g_wgk16);
    cudaGetSymbolAddress((void**)&wgk8,  g_wgk8);

    cudaFuncSetAttribute((const void*)conv_mma<3, 7, 32, false, true>,
                         cudaFuncAttributeMaxDynamicSharedMemorySize, GATE_SMEM);
    cudaFuncSetAttribute((const void*)conv_mma<5, 5, 40, false, false>,
                         cudaFuncAttributeMaxDynamicSharedMemorySize, C5_SMEM);
    cudaFuncSetAttribute((const void*)conv_mma<5, 5, 40, true, false>,
                         cudaFuncAttributeMaxDynamicSharedMemorySize, C5_SMEM);

    zero_state<<<1024, 256>>>();
    pack_gates<<<(56 * 360 + 255) / 256, 256>>>(Wf, bf, Wi, bi, Wc, bc, Wq, bq);
    pack_k16<25, 5><<<(25 * 2 * 5 * 2 * 32 + 255) / 256, 256>>>(W0, w0k16);
    pack_k8 <25, 5><<<(25 * 5 * 2 * 32 + 255) / 256, 256>>>(W0, w0k8);
    pack_k16<25, 5><<<(25 * 2 * 5 * 2 * 32 + 255) / 256, 256>>>(W1, w1k16);
    pack_k8 <25, 5><<<(25 * 5 * 2 * 32 + 255) / 256, 256>>>(W1, w1k8);
    pack_k16<9, 7><<<(9 * 2 * 7 * 2 * 32 + 255) / 256, 256>>>(Wg, wgk16);
    pack_k8 <9, 7><<<(9 * 7 * 2 * 32 + 255) / 256, 256>>>(Wg, wgk8);

    for (int t = 0; t < ND; t++) {
        for (int s = 0; s < 2; s++) {
            const float* x = (s == 0 ? x1 : x2) + (size_t)t * 32 * HW;

            // 1) gate conv 3x3 (mma) + fused LSTM pointwise -> r = [c'|sig(q)]
            conv_mma<3, 7, 32, false, true>
                <<<dim3(6, 48, NB), 128, GATE_SMEM>>>(
                    x, ND * 32 * HW, hs, 8 * HW, wgk16, wgk8, bg,
                    nullptr, nullptr, nullptr, r);

            // 2) conv0 5x5 40->40 (mma, raw output)
            conv_mma<5, 5, 40, false, false>
                <<<dim3(6, 48, NB), 128, C5_SMEM>>>(
                    r, 40 * HW, nullptr, 0, w0k16, w0k8, nullptr,
                    nullptr, nullptr, nullptr, y0);

            // 3) BN partials for y0
            bn_partial<<<dim3(40, NB), 256>>>(y0, psum);

            // 4) conv1 5x5 40->40 (mma, BN+ReLU of y0 fused on input)
            conv_mma<5, 5, 40, true, false>
                <<<dim3(6, 48, NB), 128, C5_SMEM>>>(
                    y0, 40 * HW, nullptr, 0, w1k16, w1k8, nullptr,
                    psum, g0, be0, y1);

            // 5) BN partials for y1
            bn_partial<<<dim3(40, NB), 256>>>(y1, psum);

            // 6) new h-state: conv 3x3 40->8 (BN+ReLU fused on input)
            conv_generic<40, 40, 8, 3, 16, 8, 2, true, true>
                <<<dim3(6, 12, NB), dim3(32, 8, 2)>>>(
                    y1, 40 * HW, nullptr, 0, Wh, bh,
                    psum, g1, be1, hs, 8 * HW, HW);

            // 7) output head: conv 5x5 40->3 into d_out (b,3,d,H,W) slice
            conv_generic<40, 40, 3, 5, 16, 8, 1, true, true>
                <<<dim3(6, 12, NB), dim3(32, 8, 1)>>>(
                    y1, 40 * HW, nullptr, 0, W2, b2w,
                    psum, g1, be1,
                    out + (size_t)s * (NB * 3 * ND * HW) + (size_t)t * HW,
                    3 * ND * HW, ND * HW);
        }
    }
}

// round 8
// speedup vs baseline: 2.9775x; 1.4849x over previous
#include <cuda_runtime.h>
#include <cuda_bf16.h>
#include <cstdint>
#include <math.h>

#define HH 192
#define WWID 192
#define HW (192*192)
#define NB 4
#define ND 8

// ======================= mma / ldmatrix helpers (sm_80+ PTX) ================
__device__ __forceinline__ void ldmx4(uint32_t addr, uint32_t* r) {
    asm volatile("ldmatrix.sync.aligned.m8n8.x4.shared.b16 {%0,%1,%2,%3}, [%4];"
        : "=r"(r[0]), "=r"(r[1]), "=r"(r[2]), "=r"(r[3]) : "r"(addr));
}
__device__ __forceinline__ void ldmx2(uint32_t addr, uint32_t* r) {
    asm volatile("ldmatrix.sync.aligned.m8n8.x2.shared.b16 {%0,%1}, [%2];"
        : "=r"(r[0]), "=r"(r[1]) : "r"(addr));
}
__device__ __forceinline__ void mma16816(float* d, const uint32_t* a, uint2 b) {
    asm volatile("mma.sync.aligned.m16n8k16.row.col.f32.bf16.bf16.f32 "
        "{%0,%1,%2,%3}, {%4,%5,%6,%7}, {%8,%9}, {%0,%1,%2,%3};"
        : "+f"(d[0]), "+f"(d[1]), "+f"(d[2]), "+f"(d[3])
        : "r"(a[0]), "r"(a[1]), "r"(a[2]), "r"(a[3]), "r"(b.x), "r"(b.y));
}
__device__ __forceinline__ void mma1688(float* d, const uint32_t* a, uint32_t b) {
    asm volatile("mma.sync.aligned.m16n8k8.row.col.f32.bf16.bf16.f32 "
        "{%0,%1,%2,%3}, {%4,%5}, {%6}, {%0,%1,%2,%3};"
        : "+f"(d[0]), "+f"(d[1]), "+f"(d[2]), "+f"(d[3])
        : "r"(a[0]), "r"(a[1]), "r"(b));
}
__device__ __forceinline__ uint32_t smem_u32(const void* p) {
    uint32_t a;
    asm("{ .reg .u64 t; cvta.to.shared.u64 t, %1; cvt.u32.u64 %0, t; }" : "=r"(a) : "l"(p));
    return a;
}
__device__ __forceinline__ unsigned short bfbits(float v) {
    return __bfloat16_as_ushort(__float2bfloat16(v));
}
__device__ __forceinline__ float fsig(float x) {
    return __fdividef(1.f, 1.f + __expf(-x));
}
__device__ __forceinline__ float ftanh(float x) {
    return 1.f - __fdividef(2.f, __expf(2.f * x) + 1.f);
}

// ======================= scratch ============================================
__device__ float g_hs[NB * 8 * HW];
__device__ float g_r [NB * 40 * HW];     // [c_state(8) | q(32)]
__device__ float g_y0[NB * 40 * HW];
__device__ float g_y1[NB * 40 * HW];
__device__ float g_psum[2 * 40 * NB];
__device__ float g_Wg[56 * 40 * 9];
__device__ float g_bg[56];
__device__ float g_Who[16 * 40 * 25];    // fused h(3x3 embedded) + out(5x5) weights
__device__ float g_bho[16];
// packed mma weight fragments (k16 pairs + k8 tail), bf16 hi/lo terms
__device__ uint2    g_w0k16[25 * 2 * 5 * 2 * 32];
__device__ uint32_t g_w0k8 [25 * 5 * 2 * 32];
__device__ uint2    g_w1k16[25 * 2 * 5 * 2 * 32];
__device__ uint32_t g_w1k8 [25 * 5 * 2 * 32];
__device__ uint2    g_wgk16[9 * 2 * 7 * 2 * 32];
__device__ uint32_t g_wgk8 [9 * 7 * 2 * 32];
__device__ uint2    g_whk16[25 * 2 * 2 * 2 * 32];
__device__ uint32_t g_whk8 [25 * 2 * 2 * 32];

// ======================= init kernels =======================================
__global__ void zero_state() {
    int stride = gridDim.x * blockDim.x;
    int i0 = blockIdx.x * blockDim.x + threadIdx.x;
    for (int i = i0; i < NB * 8 * HW; i += stride) g_hs[i] = 0.f;
    for (int i = i0; i < NB * 40 * HW; i += stride) g_r[i] = 0.f;
}

__global__ void pack_gates(const float* __restrict__ Wf, const float* __restrict__ bf,
                           const float* __restrict__ Wi, const float* __restrict__ bi,
                           const float* __restrict__ Wc, const float* __restrict__ bc,
                           const float* __restrict__ Wq, const float* __restrict__ bq) {
    const int WSZ = 40 * 9;
    int i = blockIdx.x * blockDim.x + threadIdx.x;
    if (i < 56 * WSZ) {
        int cout = i / WSZ, rest = i - cout * WSZ;
        float v;
        if (cout < 8)       v = Wf[cout * WSZ + rest];
        else if (cout < 16) v = Wi[(cout - 8) * WSZ + rest];
        else if (cout < 24) v = Wc[(cout - 16) * WSZ + rest];
        else                v = Wq[(cout - 24) * WSZ + rest];
        g_Wg[i] = v;
    }
    if (i < 56) {
        float v;
        if (i < 8)       v = bf[i];
        else if (i < 16) v = bi[i - 8];
        else if (i < 24) v = bc[i - 16];
        else             v = bq[i - 24];
        g_bg[i] = v;
    }
}

// fused h+out weights: n<8 = Wh (3x3 embedded center of 5x5), n in 8..10 = W2
__global__ void build_whout(const float* __restrict__ Wh, const float* __restrict__ bh,
                            const float* __restrict__ W2, const float* __restrict__ b2w) {
    int i = blockIdx.x * blockDim.x + threadIdx.x;
    if (i < 16 * 40 * 25) {
        int tap = i % 25; int rest = i / 25;
        int k = rest % 40; int nn = rest / 40;
        int ky = tap / 5, kx = tap % 5;
        float v = 0.f;
        if (nn < 8) {
            if (ky >= 1 && ky <= 3 && kx >= 1 && kx <= 3)
                v = Wh[(nn * 40 + k) * 9 + (ky - 1) * 3 + (kx - 1)];
        } else if (nn < 11) {
            v = W2[((nn - 8) * 40 + k) * 25 + tap];
        }
        g_Who[i] = v;
    }
    if (i < 16) g_bho[i] = (i < 8) ? bh[i] : (i < 11 ? b2w[i - 8] : 0.f);
}

// W layout expected: W[(n*40 + k)*TAPS + tap]
template<int TAPS, int NT>
__global__ void pack_k16(const float* __restrict__ W, uint2* __restrict__ dst) {
    int i = blockIdx.x * blockDim.x + threadIdx.x;
    if (i >= TAPS * 2 * NT * 2 * 32) return;
    int lane = i & 31; int r = i >> 5;
    int term = r & 1; r >>= 1;
    int nt = r % NT;  r /= NT;
    int kt = r & 1;   int tap = r >> 1;
    int nn = nt * 8 + (lane >> 2);
    int k0 = kt * 16 + (lane & 3) * 2;
    unsigned short h[4];
#pragma unroll
    for (int j = 0; j < 4; j++) {
        int kk = k0 + (j & 1) + (j >> 1) * 8;
        float v = W[(nn * 40 + kk) * TAPS + tap];
        unsigned short hb = bfbits(v);
        if (term == 0) h[j] = hb;
        else h[j] = bfbits(v - __bfloat162float(__ushort_as_bfloat16(hb)));
    }
    dst[i] = make_uint2((uint32_t)h[0] | ((uint32_t)h[1] << 16),
                        (uint32_t)h[2] | ((uint32_t)h[3] << 16));
}

template<int TAPS, int NT>
__global__ void pack_k8(const float* __restrict__ W, uint32_t* __restrict__ dst) {
    int i = blockIdx.x * blockDim.x + threadIdx.x;
    if (i >= TAPS * NT * 2 * 32) return;
    int lane = i & 31; int r = i >> 5;
    int term = r & 1; r >>= 1;
    int nt = r % NT;  int tap = r / NT;
    int nn = nt * 8 + (lane >> 2);
    int k0 = 32 + (lane & 3) * 2;
    unsigned short h[2];
#pragma unroll
    for (int j = 0; j < 2; j++) {
        int kk = k0 + j;
        float v = W[(nn * 40 + kk) * TAPS + tap];
        unsigned short hb = bfbits(v);
        if (term == 0) h[j] = hb;
        else h[j] = bfbits(v - __bfloat162float(__ushort_as_bfloat16(hb)));
    }
    dst[i] = (uint32_t)h[0] | ((uint32_t)h[1] << 16);
}

// ======================= generic mma conv (CIN=40, bf16 3-term, K=40) =======
// CTA: 256 thr / 8 warps; out tile 32x8 pixels; COUT = NT*8.
// MODE 0: plain 40-ch output.
// MODE 1: LSTM epilogue -> out = r buffer (old c in ch0-7), bias = gate biases.
// MODE 2: HOUT epilogue -> out = h-state (8ch) + out2 = p_depth (3ch), biased.
#define ASTRIDE 56
#define NTHR 256

template<int KK, int NT, int CA, bool PREOP, int MODE>
__global__ void __launch_bounds__(NTHR, 2)
conv_mma(const float* __restrict__ inA, int strideA,
         const float* __restrict__ inB, int strideB,
         const uint2* __restrict__ wk16,
         const uint32_t* __restrict__ wk8,
         const float* __restrict__ bias,
         const float* __restrict__ psum,
         const float* __restrict__ gamma,
         const float* __restrict__ beta,
         float* __restrict__ out,
         float* __restrict__ out2)
{
    constexpr int TW = 32 + KK - 1;
    constexpr int TH = 8 + KK - 1;
    constexpr int NPIX = TW * TH;
    constexpr int PADK = KK / 2;
    constexpr int APL = NPIX * ASTRIDE * 2;     // bytes per bf16 plane

    extern __shared__ char dsm[];
    __shared__ float s_sc[40], s_sh[40];
    __shared__ float s_bias[56];
    __nv_bfloat16* Ah = (__nv_bfloat16*)dsm;
    __nv_bfloat16* Al = (__nv_bfloat16*)(dsm + APL);

    const int tid = threadIdx.x;
    const int w = tid >> 5, lane = tid & 31;
    const int bx = blockIdx.x, by = blockIdx.y, n = blockIdx.z;

    if constexpr (MODE == 1) {
        if (tid < 56) s_bias[tid] = bias[tid];
    }
    if constexpr (MODE == 2) {
        if (tid < 16) s_bias[tid] = bias[tid];
    }
    if constexpr (PREOP) {
        if (tid < 40) {
            float s = 0.f, s2 = 0.f;
#pragma unroll
            for (int nn = 0; nn < NB; nn++) {
                s  += psum[tid * NB + nn];
                s2 += psum[40 * NB + tid * NB + nn];
            }
            const float Ninv = 1.f / (float)(NB * HW);
            float mean = s * Ninv;
            float var  = s2 * Ninv - mean * mean;
            float scv  = gamma[tid] * rsqrtf(var + 1e-5f);
            s_sc[tid] = scv;
            s_sh[tid] = beta[tid] - mean * scv;
        }
        __syncthreads();
    }

    // ---- stage input tile (fused concat), split bf16 hi/lo -----------------
    const int x0 = bx * 32 - PADK, y0 = by * 8 - PADK;
    for (int i = tid; i < 40 * NPIX; i += NTHR) {
        int cin = i / NPIX, pix = i - cin * NPIX;
        int pr = pix / TW, pc = pix - pr * TW;
        int yy = y0 + pr, xx = x0 + pc;
        float v = 0.f;
        if (yy >= 0 && yy < HH && xx >= 0 && xx < WWID) {
            const float* src = (cin < CA)
                ? (inA + (size_t)n * strideA + (size_t)cin * HW)
                : (inB + (size_t)n * strideB + (size_t)(cin - CA) * HW);
            v = src[yy * WWID + xx];
            if constexpr (PREOP) v = fmaxf(fmaf(s_sc[cin], v, s_sh[cin]), 0.f);
        }
        __nv_bfloat16 h = __float2bfloat16(v);
        __nv_bfloat16 l = __float2bfloat16(v - __bfloat162float(h));
        Ah[pix * ASTRIDE + cin] = h;
        Al[pix * ASTRIDE + cin] = l;
    }
    __syncthreads();

    const uint32_t ah_base = smem_u32(Ah);
    const uint32_t al_base = ah_base + APL;
    const int lrow = lane & 15;
    const int lcolB = (lane >> 4) * 16;

    float d[2][NT][4];
#pragma unroll
    for (int mt = 0; mt < 2; mt++)
#pragma unroll
        for (int nt = 0; nt < NT; nt++)
#pragma unroll
            for (int j = 0; j < 4; j++) d[mt][nt][j] = 0.f;

    for (int tap = 0; tap < KK * KK; tap++) {
        int ky = tap / KK, kx = tap - ky * KK;
        int rowbase = (w + ky) * TW + kx;

        uint32_t a_h[2][2][4], a_l[2][2][4];   // [kt][mt]
        uint32_t a_h8[2][2], a_l8[2][2];       // [mt]
#pragma unroll
        for (int mt = 0; mt < 2; mt++) {
            uint32_t rb = (uint32_t)(rowbase + mt * 16 + lrow) * (ASTRIDE * 2);
            ldmx4(ah_base + rb + lcolB, a_h[0][mt]);
            ldmx4(ah_base + rb + 32 + lcolB, a_h[1][mt]);
            ldmx2(ah_base + rb + 64, a_h8[mt]);
            ldmx4(al_base + rb + lcolB, a_l[0][mt]);
            ldmx4(al_base + rb + 32 + lcolB, a_l[1][mt]);
            ldmx2(al_base + rb + 64, a_l8[mt]);
        }

        const uint2* wt16 = wk16 + tap * (2 * NT * 2 * 32);
        const uint32_t* wt8 = wk8 + tap * (NT * 2 * 32);
#pragma unroll
        for (int kt = 0; kt < 2; kt++) {
#pragma unroll
            for (int nt = 0; nt < NT; nt++) {
                uint2 bh = wt16[((kt * NT + nt) * 2 + 0) * 32 + lane];
                uint2 bl = wt16[((kt * NT + nt) * 2 + 1) * 32 + lane];
#pragma unroll
                for (int mt = 0; mt < 2; mt++) {
                    mma16816(d[mt][nt], a_h[kt][mt], bh);
                    mma16816(d[mt][nt], a_l[kt][mt], bh);
                    mma16816(d[mt][nt], a_h[kt][mt], bl);
                }
            }
        }
#pragma unroll
        for (int nt = 0; nt < NT; nt++) {
            uint32_t bh8 = wt8[(nt * 2 + 0) * 32 + lane];
            uint32_t bl8 = wt8[(nt * 2 + 1) * 32 + lane];
#pragma unroll
            for (int mt = 0; mt < 2; mt++) {
                mma1688(d[mt][nt], a_h8[mt], bh8);
                mma1688(d[mt][nt], a_l8[mt], bh8);
                mma1688(d[mt][nt], a_h8[mt], bl8);
            }
        }
    }

    if constexpr (MODE == 1) {
        // ---- stash D (256 pix x 56 ch) to smem, then LSTM pointwise --------
        __syncthreads();                      // A planes dead; reuse dsm
        float* sd = (float*)dsm;              // [256][57]
#pragma unroll
        for (int mt = 0; mt < 2; mt++) {
            int px = mt * 16 + (lane >> 2);
#pragma unroll
            for (int nt = 0; nt < NT; nt++) {
                int c = nt * 8 + (lane & 3) * 2;
                sd[(w * 32 + px) * 57 + c]           = d[mt][nt][0];
                sd[(w * 32 + px) * 57 + c + 1]       = d[mt][nt][1];
                sd[(w * 32 + px + 8) * 57 + c]       = d[mt][nt][2];
                sd[(w * 32 + px + 8) * 57 + c + 1]   = d[mt][nt][3];
            }
        }
        __syncthreads();
        const float* sp = sd + tid * 57;
        int gy = by * 8 + (tid >> 5);
        int gx = bx * 32 + (tid & 31);
        float* rb = out + (size_t)n * 40 * HW + gy * WWID + gx;
#pragma unroll
        for (int c = 0; c < 8; c++) {
            float f  = fsig(sp[c] + s_bias[c]);
            float ii = fsig(sp[8 + c] + s_bias[8 + c]);
            float gg = ftanh(sp[16 + c] + s_bias[16 + c]);
            float co = rb[(size_t)c * HW];
            rb[(size_t)c * HW] = f * co + ii * gg;
        }
#pragma unroll
        for (int j = 0; j < 32; j++) {
            rb[(size_t)(8 + j) * HW] = fsig(sp[24 + j] + s_bias[24 + j]);
        }
    } else if constexpr (MODE == 2) {
        // ---- dual epilogue: nt0 -> h-state (8ch), nt1 -> p_depth (3ch) -----
        const int gy = by * 8 + w;
#pragma unroll
        for (int mt = 0; mt < 2; mt++) {
            int gx = bx * 32 + mt * 16 + (lane >> 2);
            {
                int c = (lane & 3) * 2;
                float* hb = out + ((size_t)n * 8 + c) * HW + gy * WWID + gx;
                hb[0]      = d[mt][0][0] + s_bias[c];
                hb[HW]     = d[mt][0][1] + s_bias[c + 1];
                hb[8]      = d[mt][0][2] + s_bias[c];
                hb[HW + 8] = d[mt][0][3] + s_bias[c + 1];
            }
            {
                int oc = (lane & 3) * 2;
                if (oc < 3) {
                    float* ob = out2 + (size_t)n * 3 * ND * HW
                              + (size_t)oc * ND * HW + gy * WWID + gx;
                    ob[0] = d[mt][1][0] + s_bias[8 + oc];
                    ob[8] = d[mt][1][2] + s_bias[8 + oc];
                    if (oc + 1 < 3) {
                        ob[(size_t)ND * HW]     = d[mt][1][1] + s_bias[9 + oc];
                        ob[(size_t)ND * HW + 8] = d[mt][1][3] + s_bias[9 + oc];
                    }
                }
            }
        }
    } else {
        const int gy = by * 8 + w;
#pragma unroll
        for (int mt = 0; mt < 2; mt++) {
            int gx = bx * 32 + mt * 16 + (lane >> 2);
#pragma unroll
            for (int nt = 0; nt < NT; nt++) {
                int c = nt * 8 + (lane & 3) * 2;
                float* ob = out + ((size_t)n * 40 + c) * HW + gy * WWID + gx;
                ob[0]      = d[mt][nt][0];
                ob[HW]     = d[mt][nt][1];
                ob[8]      = d[mt][nt][2];
                ob[HW + 8] = d[mt][nt][3];
            }
        }
    }
}

#define C5_SMEM   (36 * 12 * ASTRIDE * 2 * 2)                         // 96768
#define GATE_A    (34 * 10 * ASTRIDE * 2 * 2)                         // 76160
#define GATE_SD   (256 * 57 * 4)                                      // 58368
#define GATE_SMEM (GATE_A > GATE_SD ? GATE_A : GATE_SD)

// ======================= BN partial sums ====================================
__global__ void bn_partial(const float* __restrict__ y, float* __restrict__ psum) {
    int c = blockIdx.x, n = blockIdx.y;
    const float4* yp = (const float4*)(y + ((size_t)n * 40 + c) * HW);
    float s = 0.f, s2 = 0.f;
    for (int i = threadIdx.x; i < HW / 4; i += blockDim.x) {
        float4 v = yp[i];
        s += v.x + v.y + v.z + v.w;
        s2 = fmaf(v.x, v.x, s2); s2 = fmaf(v.y, v.y, s2);
        s2 = fmaf(v.z, v.z, s2); s2 = fmaf(v.w, v.w, s2);
    }
    __shared__ float rs[256], rs2[256];
    rs[threadIdx.x] = s; rs2[threadIdx.x] = s2;
    __syncthreads();
    for (int off = 128; off > 0; off >>= 1) {
        if (threadIdx.x < off) {
            rs[threadIdx.x] += rs[threadIdx.x + off];
            rs2[threadIdx.x] += rs2[threadIdx.x + off];
        }
        __syncthreads();
    }
    if (threadIdx.x == 0) {
        psum[c * NB + n] = rs[0];
        psum[40 * NB + c * NB + n] = rs2[0];
    }
}

// ======================= driver =============================================
extern "C" void kernel_launch(void* const* d_in, const int* in_sizes, int n_in,
                              void* d_out, int out_size) {
    const float* x1  = (const float*)d_in[0];
    const float* x2  = (const float*)d_in[1];
    const float* Wf  = (const float*)d_in[2];
    const float* bf  = (const float*)d_in[3];
    const float* Wi  = (const float*)d_in[4];
    const float* bi  = (const float*)d_in[5];
    const float* Wc  = (const float*)d_in[6];
    const float* bc  = (const float*)d_in[7];
    const float* Wq  = (const float*)d_in[8];
    const float* bq  = (const float*)d_in[9];
    const float* W0  = (const float*)d_in[10];
    const float* g0  = (const float*)d_in[11];
    const float* be0 = (const float*)d_in[12];
    const float* W1  = (const float*)d_in[13];
    const float* g1  = (const float*)d_in[14];
    const float* be1 = (const float*)d_in[15];
    const float* W2  = (const float*)d_in[16];
    const float* b2w = (const float*)d_in[17];
    const float* Wh  = (const float*)d_in[18];
    const float* bh  = (const float*)d_in[19];
    float* out = (float*)d_out;

    float *hs, *r, *y0, *y1, *psum, *Wg, *bg, *Who, *bho;
    uint2 *w0k16, *w1k16, *wgk16, *whk16;
    uint32_t *w0k8, *w1k8, *wgk8, *whk8;
    cudaGetSymbolAddress((void**)&hs,    g_hs);
    cudaGetSymbolAddress((void**)&r,     g_r);
    cudaGetSymbolAddress((void**)&y0,    g_y0);
    cudaGetSymbolAddress((void**)&y1,    g_y1);
    cudaGetSymbolAddress((void**)&psum,  g_psum);
    cudaGetSymbolAddress((void**)&Wg,    g_Wg);
    cudaGetSymbolAddress((void**)&bg,    g_bg);
    cudaGetSymbolAddress((void**)&Who,   g_Who);
    cudaGetSymbolAddress((void**)&bho,   g_bho);
    cudaGetSymbolAddress((void**)&w0k16, g_w0k16);
    cudaGetSymbolAddress((void**)&w0k8,  g_w0k8);
    cudaGetSymbolAddress((void**)&w1k16, g_w1k16);
    cudaGetSymbolAddress((void**)&w1k8,  g_w1k8);
    cudaGetSymbolAddress((void**)&wgk16, g_wgk16);
    cudaGetSymbolAddress((void**)&wgk8,  g_wgk8);
    cudaGetSymbolAddress((void**)&whk16, g_whk16);
    cudaGetSymbolAddress((void**)&whk8,  g_whk8);

    cudaFuncSetAttribute((const void*)conv_mma<3, 7, 32, false, 1>,
                         cudaFuncAttributeMaxDynamicSharedMemorySize, GATE_SMEM);
    cudaFuncSetAttribute((const void*)conv_mma<5, 5, 40, false, 0>,
                         cudaFuncAttributeMaxDynamicSharedMemorySize, C5_SMEM);
    cudaFuncSetAttribute((const void*)conv_mma<5, 5, 40, true, 0>,
                         cudaFuncAttributeMaxDynamicSharedMemorySize, C5_SMEM);
    cudaFuncSetAttribute((const void*)conv_mma<5, 2, 40, true, 2>,
                         cudaFuncAttributeMaxDynamicSharedMemorySize, C5_SMEM);

    zero_state<<<1024, 256>>>();
    pack_gates<<<(56 * 360 + 255) / 256, 256>>>(Wf, bf, Wi, bi, Wc, bc, Wq, bq);
    build_whout<<<(16 * 40 * 25 + 255) / 256, 256>>>(Wh, bh, W2, b2w);
    pack_k16<25, 5><<<(25 * 2 * 5 * 2 * 32 + 255) / 256, 256>>>(W0, w0k16);
    pack_k8 <25, 5><<<(25 * 5 * 2 * 32 + 255) / 256, 256>>>(W0, w0k8);
    pack_k16<25, 5><<<(25 * 2 * 5 * 2 * 32 + 255) / 256, 256>>>(W1, w1k16);
    pack_k8 <25, 5><<<(25 * 5 * 2 * 32 + 255) / 256, 256>>>(W1, w1k8);
    pack_k16<9, 7><<<(9 * 2 * 7 * 2 * 32 + 255) / 256, 256>>>(Wg, wgk16);
    pack_k8 <9, 7><<<(9 * 7 * 2 * 32 + 255) / 256, 256>>>(Wg, wgk8);
    pack_k16<25, 2><<<(25 * 2 * 2 * 2 * 32 + 255) / 256, 256>>>(Who, whk16);
    pack_k8 <25, 2><<<(25 * 2 * 2 * 32 + 255) / 256, 256>>>(Who, whk8);

    for (int t = 0; t < ND; t++) {
        for (int s = 0; s < 2; s++) {
            const float* x = (s == 0 ? x1 : x2) + (size_t)t * 32 * HW;
            float* oslice = out + (size_t)s * (NB * 3 * ND * HW) + (size_t)t * HW;

            // 1) gate conv 3x3 (mma) + fused LSTM pointwise -> r = [c'|sig(q)]
            conv_mma<3, 7, 32, false, 1>
                <<<dim3(6, 24, NB), NTHR, GATE_SMEM>>>(
                    x, ND * 32 * HW, hs, 8 * HW, wgk16, wgk8, bg,
                    nullptr, nullptr, nullptr, r, nullptr);

            // 2) conv0 5x5 40->40 (mma, raw output)
            conv_mma<5, 5, 40, false, 0>
                <<<dim3(6, 24, NB), NTHR, C5_SMEM>>>(
                    r, 40 * HW, nullptr, 0, w0k16, w0k8, nullptr,
                    nullptr, nullptr, nullptr, y0, nullptr);

            // 3) BN partials for y0
            bn_partial<<<dim3(40, NB), 256>>>(y0, psum);

            // 4) conv1 5x5 40->40 (mma, BN+ReLU of y0 fused on input)
            conv_mma<5, 5, 40, true, 0>
                <<<dim3(6, 24, NB), NTHR, C5_SMEM>>>(
                    y0, 40 * HW, nullptr, 0, w1k16, w1k8, nullptr,
                    psum, g0, be0, y1, nullptr);

            // 5) BN partials for y1
            bn_partial<<<dim3(40, NB), 256>>>(y1, psum);

            // 6) fused h-state (3x3 embedded) + output head (5x5), mma
            conv_mma<5, 2, 40, true, 2>
                <<<dim3(6, 24, NB), NTHR, C5_SMEM>>>(
                    y1, 40 * HW, nullptr, 0, whk16, whk8, bho,
                    psum, g1, be1, hs, oslice);
        }
    }
}